// round 7
// baseline (speedup 1.0000x reference)
#include <cuda_runtime.h>
#include <cuda_fp16.h>
#include <stdint.h>

#define Bb 4
#define Nn 256
#define Dd 32
#define Hh 512
#define Kk 256

// device scratch
__device__ uint4 g_tmph[((size_t)Bb*Nn*Hh*Dd*2)/16];   // fp16 TMP per SLOT [s][h 512][c 32]
__device__ uint4 g_w2t [(8*Kk*128)/16];                 // 256 KB fp16 W2^T chunks, XOR-swizzled
__device__ int   g_jlist[Bb*Nn];
__device__ int   g_jcnt[Bb];
__device__ int   g_gilist[Bb*Nn];
__device__ int   g_slot[Bb*Nn];
__device__ int   g_total;

// ---------------- helpers ----------------
__device__ __forceinline__ uint32_t s2u(const void* p) {
    uint32_t a;
    asm("{ .reg .u64 t; cvta.to.shared.u64 t, %1; cvt.u32.u64 %0, t; }" : "=r"(a) : "l"(p));
    return a;
}
__device__ __forceinline__ void mbar_init(uint32_t m, uint32_t c) {
    asm volatile("mbarrier.init.shared.b64 [%0], %1;" :: "r"(m), "r"(c) : "memory");
}
__device__ __forceinline__ void mbar_expect(uint32_t m, uint32_t bytes) {
    asm volatile("mbarrier.arrive.expect_tx.shared.b64 _, [%0], %1;" :: "r"(m), "r"(bytes) : "memory");
}
__device__ __forceinline__ void mbar_wait(uint32_t m, uint32_t ph) {
    asm volatile(
        "{\n\t.reg .pred P;\n\t"
        "LW%=:\n\t"
        "mbarrier.try_wait.parity.shared.b64 P, [%0], %1, 0x989680;\n\t"
        "@P bra LD%=;\n\t"
        "bra LW%=;\n\t"
        "LD%=:\n\t}"
        :: "r"(m), "r"(ph) : "memory");
}
__device__ __forceinline__ void bulk_g2s(uint32_t dst, const void* src, uint32_t bytes, uint32_t mbar) {
    asm volatile("cp.async.bulk.shared::cluster.global.mbarrier::complete_tx::bytes [%0], [%1], %2, [%3];"
                 :: "r"(dst), "l"(src), "r"(bytes), "r"(mbar) : "memory");
}
__device__ __forceinline__ void mma16816(float d[4], const uint32_t a[4], uint32_t b0, uint32_t b1) {
    asm volatile("mma.sync.aligned.m16n8k16.row.col.f32.f16.f16.f32 "
                 "{%0,%1,%2,%3}, {%4,%5,%6,%7}, {%8,%9}, {%0,%1,%2,%3};"
                 : "+f"(d[0]), "+f"(d[1]), "+f"(d[2]), "+f"(d[3])
                 : "r"(a[0]), "r"(a[1]), "r"(a[2]), "r"(a[3]), "r"(b0), "r"(b1));
}
__device__ __forceinline__ void ldsm4(uint32_t r[4], uint32_t addr) {
    asm volatile("ldmatrix.sync.aligned.m8n8.x4.shared.b16 {%0,%1,%2,%3}, [%4];"
                 : "=r"(r[0]), "=r"(r[1]), "=r"(r[2]), "=r"(r[3]) : "r"(addr));
}

// ---------------- prep kernels ----------------
// single block: per-batch j-lists + global compacted i-list + per-bi slot
__global__ void __launch_bounds__(1024) prep_mask_kernel(const float* __restrict__ mm) {
    __shared__ int wcnt[32], woff[33];
    int t = threadIdx.x, w = t >> 5, lane = t & 31, b = t >> 8;
    int act = (mm[t] != 0.f);
    unsigned bal = __ballot_sync(0xffffffffu, act);
    if (lane == 0) wcnt[w] = __popc(bal);
    __syncthreads();
    if (t == 0) {
        int s = 0;
        for (int q = 0; q < 32; q++) { woff[q] = s; s += wcnt[q]; }
        woff[32] = s; g_total = s;
        for (int bb = 0; bb < 4; bb++) g_jcnt[bb] = woff[bb * 8 + 8] - woff[bb * 8];
    }
    __syncthreads();
    if (act) {
        int pg = woff[w] + __popc(bal & ((1u << lane) - 1u));
        g_jlist[b * Nn + (pg - woff[b * 8])] = t & 255;
        g_gilist[pg] = t;
        g_slot[t] = pg;
    }
}

// W2T chunk layout: [hc][k row 128B][64 h halves], bytes XOR-swizzled by ((k&7)<<4).
__global__ void __launch_bounds__(256) prep_w2t_kernel(const float* __restrict__ W2) {
    int idx = blockIdx.x * 256 + threadIdx.x;
    int hc  = idx >> 13;
    int rem = idx & 8191;
    int k   = rem >> 5;
    int hcol = (rem & 31) * 2;
    __half2 v = __floats2half2_rn(W2[(hc * 64 + hcol) * Kk + k], W2[(hc * 64 + hcol + 1) * Kk + k]);
    uint32_t byt = (uint32_t)hc * 32768u + (uint32_t)k * 128u
                 + (((uint32_t)hcol * 2u) ^ (((uint32_t)k & 7u) << 4));
    *(__half2*)((char*)g_w2t + byt) = v;
}

// TMP[slot][h][c] = sum_a z[gilist[slot]][a] * W1[(a*32+c)*512 + h]; active slots only.
#define PT_ZS   0
#define PT_W1S  8448
#define PT_STG  41728
#define PT_SMEM 82688
__global__ void __launch_bounds__(256) prep_tmp_kernel(const float* __restrict__ z,
                                                       const float* __restrict__ W1) {
    extern __shared__ char psm[];
    float* zs  = (float*)(psm + PT_ZS);     // [64][33]
    float* W1s = (float*)(psm + PT_W1S);    // [32][260]
    char*  stg = psm + PT_STG;              // [16][32 h][40 halves pitch]
    __shared__ int giS[64];

    const int total = g_total;
    int it = blockIdx.x;
    if (it * 64 >= total) return;
    int ht = blockIdx.y, t = threadIdx.x;
    int c8 = t >> 5, hl = t & 31;

    if (t < 64) giS[t] = (it * 64 + t < total) ? g_gilist[it * 64 + t] : -1;
    __syncthreads();

    for (int idx = t; idx < 64 * 32; idx += 256) {
        int r = idx >> 5, a = idx & 31;
        zs[r * 33 + a] = (giS[r] >= 0) ? z[giS[r] * Dd + a] : 0.f;
    }
    __syncthreads();

    for (int ig = 0; ig < 4; ig++) {
        for (int fc = 0; fc < 4; fc++) {
            __syncthreads();
            {
                int c = fc * 8 + c8, h = ht * 32 + hl;
                #pragma unroll
                for (int a = 0; a < 32; a++)
                    W1s[a * 260 + t] = W1[(a * Dd + c) * Hh + h];
            }
            __syncthreads();
            float acc[16];
            #pragma unroll
            for (int ii = 0; ii < 16; ii++) acc[ii] = 0.f;
            #pragma unroll 8
            for (int a = 0; a < 32; a++) {
                float w = W1s[a * 260 + t];
                #pragma unroll
                for (int ii = 0; ii < 16; ii++)
                    acc[ii] += w * zs[(ig * 16 + ii) * 33 + a];
            }
            int c = fc * 8 + c8;
            #pragma unroll
            for (int ii = 0; ii < 16; ii++)
                *(__half*)(stg + ii * 2560 + hl * 80 + c * 2) = __float2half(acc[ii]);
        }
        __syncthreads();
        #pragma unroll
        for (int q = 0; q < 8; q++) {
            int idx = t + 256 * q;
            int sl = idx >> 7, rem = idx & 127, h_l = rem >> 2, qt = rem & 3;
            int s = it * 64 + ig * 16 + sl;
            if (s < total) {
                uint4 v = *(const uint4*)(stg + sl * 2560 + h_l * 80 + qt * 16);
                *(uint4*)((char*)g_tmph + (size_t)s * 32768 + (ht * 32 + h_l) * 64 + qt * 16) = v;
            }
        }
        __syncthreads();
    }
}

// ---------------- main kernel ----------------
// dyn smem: zjS 4K @0 | tmpS 32K @4096 | W2 2x32K @36864 | h1 8K @102400
#define ZJ_OFF  0
#define TMP_OFF 4096
#define W2_OFF  36864
#define H1_OFF  102400
#define MAIN_SMEM 110592

__global__ void __launch_bounds__(256, 2)
decoder_hmma_kernel(const float* __restrict__ z, const float* __restrict__ mm,
                    const float* __restrict__ b1, const float* __restrict__ b2,
                    const float* __restrict__ W3, const float* __restrict__ b3,
                    float* __restrict__ out)
{
    extern __shared__ char dsm[];
    __shared__ float b1s[512], b2s[256], w3s[256], mmS[256], part[64];
    __shared__ int jlS[256];
    __shared__ __align__(8) uint64_t mbars[2];

    const int t    = threadIdx.x;
    const int w    = t >> 5;
    const int lane = t & 31;
    const int wr   = w >> 2;
    const int wc   = w & 3;
    const int lr   = lane >> 2;
    const int lc   = (lane & 3) * 2;
    const int mrow = lane & 7;
    const int mg   = lane >> 3;

    const int bi = blockIdx.x;
    const int b  = bi >> 8;
    const int i  = bi & 255;

    const uint32_t smb = s2u(dsm);
    const uint32_t mb0 = s2u(mbars);

    for (int k = t; k < 512; k += 256) b1s[k] = b1[k];
    b2s[t] = b2[t];
    w3s[t] = W3[t]; mmS[t] = mm[b * Nn + t]; jlS[t] = g_jlist[b * Nn + t];
    __syncthreads();

    const float mi = mmS[i];
    if (mi == 0.f || mmS[t] == 0.f) {
        size_t o = (size_t)bi * Nn + t;
        out[o] = 0.5f;
        out[(size_t)Bb * Nn * Nn + o] = 0.f;
    }
    if (mi == 0.f) return;

    const int sg     = g_slot[bi];
    const int Kact   = g_jcnt[b];
    const int ntiles = (Kact + 63) >> 6;
    const int totalg = ntiles * 8;

    {   // tmpS: 512 rows x 64B, XOR-swizzled by ((row>>1)&3)<<4 per 16B chunk
        const char* gsrc = (const char*)g_tmph + (size_t)sg * 32768;
        #pragma unroll
        for (int r8 = 0; r8 < 8; r8++) {
            int idx = t + 256 * r8;
            int row = idx >> 2, q = idx & 3;
            uint4 v = *(const uint4*)(gsrc + row * 64 + q * 16);
            *(uint4*)(dsm + TMP_OFF + row * 64 + ((q * 16) ^ (((row >> 1) & 3) << 4))) = v;
        }
    }
    if (t == 0) { mbar_init(mb0, 1); mbar_init(mb0 + 8, 1); }
    __syncthreads();
    if (t == 0) {
        mbar_expect(mb0, 32768);
        bulk_g2s(smb + W2_OFF, (const char*)g_w2t, 32768, mb0);
        if (totalg > 1) {
            mbar_expect(mb0 + 8, 32768);
            bulk_g2s(smb + W2_OFF + 32768, (const char*)g_w2t + 32768, 32768, mb0 + 8);
        }
    }

    const float b3v = b3[0];
    const char* h1p = dsm + H1_OFF;
    const uint32_t h1b = smb + H1_OFF;

    for (int jt = 0; jt < ntiles; jt++) {
        // per-tile zjS fill (64 rows x 64B, swizzled like tmpS) + part zero
        if (t < 64) {
            part[t] = 0.f;
            int idx = jt * 64 + t;
            char* zr = dsm + ZJ_OFF + t * 64;
            uint32_t sw = (((uint32_t)t >> 1) & 3u) << 4;
            if (idx < Kact) {
                const float4* zp = (const float4*)(z + ((size_t)b * Nn + jlS[idx]) * Dd);
                #pragma unroll
                for (int c4 = 0; c4 < 8; c4++) {
                    float4 v = zp[c4];
                    *(__half2*)(zr + (((uint32_t)(c4 * 8))     ^ sw)) = __floats2half2_rn(v.x, v.y);
                    *(__half2*)(zr + (((uint32_t)(c4 * 8 + 4)) ^ sw)) = __floats2half2_rn(v.z, v.w);
                }
            } else {
                #pragma unroll
                for (int c4 = 0; c4 < 8; c4++) {
                    *(__half2*)(zr + (((uint32_t)(c4 * 8))     ^ sw)) = __floats2half2_rn(0.f, 0.f);
                    *(__half2*)(zr + (((uint32_t)(c4 * 8 + 4)) ^ sw)) = __floats2half2_rn(0.f, 0.f);
                }
            }
        }
        __syncthreads();

        float acc2[2][8][4];
        #pragma unroll
        for (int mt = 0; mt < 2; mt++)
            #pragma unroll
            for (int nt = 0; nt < 8; nt++)
                #pragma unroll
                for (int e = 0; e < 4; e++) acc2[mt][nt][e] = 0.f;

        for (int hc = 0; hc < 8; hc++) {
            const int g = jt * 8 + hc;

            // ---- MMA1 into regs (reads zjS, tmpS only) ----
            float acc1[2][2][4];
            #pragma unroll
            for (int mt = 0; mt < 2; mt++)
                #pragma unroll
                for (int nt = 0; nt < 2; nt++)
                    #pragma unroll
                    for (int e = 0; e < 4; e++) acc1[mt][nt][e] = 0.f;

            #pragma unroll
            for (int kk = 0; kk < 2; kk++) {
                const uint32_t cb = (uint32_t)((kk * 16 + (mg >> 1) * 8) * 2);  // {0,16,32,48}
                uint32_t bf[4];
                {
                    int nh = hc * 64 + wc * 16 + (mg & 1) * 8 + mrow;
                    ldsm4(bf, smb + TMP_OFF + (uint32_t)nh * 64u + (cb ^ ((((uint32_t)nh >> 1) & 3u) << 4)));
                }
                #pragma unroll
                for (int mt = 0; mt < 2; mt++) {
                    uint32_t af[4];
                    int jr = wr * 32 + mt * 16 + (mg & 1) * 8 + mrow;
                    ldsm4(af, smb + ZJ_OFF + (uint32_t)jr * 64u + (cb ^ ((((uint32_t)jr >> 1) & 3u) << 4)));
                    mma16816(acc1[mt][0], af, bf[0], bf[2]);
                    mma16816(acc1[mt][1], af, bf[1], bf[3]);
                }
            }

            __syncthreads();   // #1: previous chunk's MMA2 reads of h1/W2 done

            // ---- h1 store (64 rows x 128B, swizzled by (row&7)<<4) ----
            #pragma unroll
            for (int mt = 0; mt < 2; mt++)
                #pragma unroll
                for (int nt = 0; nt < 2; nt++) {
                    int rl = wr * 32 + mt * 16 + lr;
                    int hl = wc * 16 + nt * 8 + lc;
                    int hg = hc * 64 + hl;
                    uint32_t sw = ((uint32_t)rl & 7u) << 4;
                    float v0 = fmaxf(acc1[mt][nt][0] + b1s[hg],     0.f);
                    float v1 = fmaxf(acc1[mt][nt][1] + b1s[hg + 1], 0.f);
                    float v2 = fmaxf(acc1[mt][nt][2] + b1s[hg],     0.f);
                    float v3 = fmaxf(acc1[mt][nt][3] + b1s[hg + 1], 0.f);
                    *(__half2*)(h1p + rl * 128 + (((uint32_t)(hl * 2)) ^ sw))       = __floats2half2_rn(v0, v1);
                    *(__half2*)(h1p + (rl + 8) * 128 + (((uint32_t)(hl * 2)) ^ sw)) = __floats2half2_rn(v2, v3);
                }

            if (t == 0 && g >= 1 && g + 1 < totalg) {     // buffer (g+1)&1 freed by sync #1
                int gn = g + 1;
                mbar_expect(mb0 + (gn & 1) * 8, 32768);
                bulk_g2s(smb + W2_OFF + (gn & 1) * 32768,
                         (const char*)g_w2t + (gn & 7) * 32768, 32768, mb0 + (gn & 1) * 8);
            }
            mbar_wait(mb0 + (g & 1) * 8, (g >> 1) & 1);
            __syncthreads();   // #2: h1 visible, W2 chunk ready

            // ---- MMA2: acc2 += h1 @ W2chunk (K=64) ----
            const uint32_t wb = smb + W2_OFF + (g & 1) * 32768u;
            #pragma unroll
            for (int kk = 0; kk < 4; kk++) {
                const uint32_t kb = (uint32_t)((kk * 16 + (mg >> 1) * 8) * 2);
                uint32_t bfs[4][4];
                #pragma unroll
                for (int p = 0; p < 4; p++) {
                    int n = wc * 64 + p * 16 + (mg & 1) * 8 + mrow;
                    ldsm4(bfs[p], wb + (uint32_t)n * 128u + (kb ^ (((uint32_t)n & 7u) << 4)));
                }
                #pragma unroll
                for (int mt = 0; mt < 2; mt++) {
                    uint32_t af[4];
                    int rl = wr * 32 + mt * 16 + (mg & 1) * 8 + mrow;
                    ldsm4(af, h1b + (uint32_t)rl * 128u + (kb ^ (((uint32_t)rl & 7u) << 4)));
                    #pragma unroll
                    for (int p = 0; p < 4; p++) {
                        mma16816(acc2[mt][2 * p],     af, bfs[p][0], bfs[p][2]);
                        mma16816(acc2[mt][2 * p + 1], af, bfs[p][1], bfs[p][3]);
                    }
                }
            }
        }

        // ---- epilogue ----
        float s[2][2] = {{0.f, 0.f}, {0.f, 0.f}};
        #pragma unroll
        for (int mt = 0; mt < 2; mt++)
            #pragma unroll
            for (int nt = 0; nt < 8; nt++) {
                int k = wc * 64 + nt * 8 + lc;
                s[mt][0] += fmaxf(acc2[mt][nt][0] + b2s[k],     0.f) * w3s[k]
                          + fmaxf(acc2[mt][nt][1] + b2s[k + 1], 0.f) * w3s[k + 1];
                s[mt][1] += fmaxf(acc2[mt][nt][2] + b2s[k],     0.f) * w3s[k]
                          + fmaxf(acc2[mt][nt][3] + b2s[k + 1], 0.f) * w3s[k + 1];
            }
        #pragma unroll
        for (int off = 1; off <= 2; off <<= 1) {
            #pragma unroll
            for (int mt = 0; mt < 2; mt++) {
                s[mt][0] += __shfl_xor_sync(0xffffffffu, s[mt][0], off);
                s[mt][1] += __shfl_xor_sync(0xffffffffu, s[mt][1], off);
            }
        }
        if ((lane & 3) == 0) {
            #pragma unroll
            for (int mt = 0; mt < 2; mt++) {
                int r0 = wr * 32 + mt * 16 + lr;
                atomicAdd(&part[r0],     s[mt][0]);
                atomicAdd(&part[r0 + 8], s[mt][1]);
            }
        }
        __syncthreads();
        if (t < 64) {
            int idx = jt * 64 + t;
            if (idx < Kact) {
                int j = jlS[idx];
                float lg = part[t] + b3v;
                size_t o = (size_t)bi * Nn + j;
                out[o] = 1.f / (1.f + __expf(-lg));
                out[(size_t)Bb * Nn * Nn + o] = lg;
            }
        }
        __syncthreads();
    }
}

extern "C" void kernel_launch(void* const* d_in, const int* in_sizes, int n_in,
                              void* d_out, int out_size)
{
    const float* z   = (const float*)d_in[0];
    const float* mmk = (const float*)d_in[1];
    const float* W1  = (const float*)d_in[3];
    const float* b1  = (const float*)d_in[4];
    const float* W2  = (const float*)d_in[5];
    const float* b2  = (const float*)d_in[6];
    const float* W3  = (const float*)d_in[7];
    const float* b3  = (const float*)d_in[8];
    float* out = (float*)d_out;

    cudaFuncSetAttribute(decoder_hmma_kernel,
                         cudaFuncAttributeMaxDynamicSharedMemorySize, MAIN_SMEM);
    cudaFuncSetAttribute(prep_tmp_kernel,
                         cudaFuncAttributeMaxDynamicSharedMemorySize, PT_SMEM);

    prep_mask_kernel<<<1, 1024>>>(mmk);
    prep_w2t_kernel<<<256, 256>>>(W2);
    prep_tmp_kernel<<<dim3(16, 16), 256, PT_SMEM>>>(z, W1);
    decoder_hmma_kernel<<<Bb * Nn, 256, MAIN_SMEM>>>(z, mmk, b1, b2, W3, b3, out);
}

// round 8
// speedup vs baseline: 1.3874x; 1.3874x over previous
#include <cuda_runtime.h>
#include <cuda_fp16.h>
#include <stdint.h>

#define Bb 4
#define Nn 256
#define Dd 32
#define Hh 512
#define Kk 256

// device scratch
__device__ uint4 g_tmph[((size_t)Bb*Nn*Hh*Dd*2)/16];   // fp16 TMP per SLOT [s][h 512][c 32]
__device__ uint4 g_w2t [(16*Kk*64)/16];                 // 256 KB fp16 W2^T: 16 chunks [k 256 x 32h], swizzled
__device__ int   g_jlist[Bb*Nn];
__device__ int   g_jcnt[Bb];
__device__ int   g_gilist[Bb*Nn];
__device__ int   g_slot[Bb*Nn];
__device__ int   g_total;

// ---------------- helpers ----------------
__device__ __forceinline__ uint32_t s2u(const void* p) {
    uint32_t a;
    asm("{ .reg .u64 t; cvta.to.shared.u64 t, %1; cvt.u32.u64 %0, t; }" : "=r"(a) : "l"(p));
    return a;
}
__device__ __forceinline__ void mbar_init(uint32_t m, uint32_t c) {
    asm volatile("mbarrier.init.shared.b64 [%0], %1;" :: "r"(m), "r"(c) : "memory");
}
__device__ __forceinline__ void mbar_expect(uint32_t m, uint32_t bytes) {
    asm volatile("mbarrier.arrive.expect_tx.shared.b64 _, [%0], %1;" :: "r"(m), "r"(bytes) : "memory");
}
__device__ __forceinline__ void mbar_wait(uint32_t m, uint32_t ph) {
    asm volatile(
        "{\n\t.reg .pred P;\n\t"
        "LW%=:\n\t"
        "mbarrier.try_wait.parity.shared.b64 P, [%0], %1, 0x989680;\n\t"
        "@P bra LD%=;\n\t"
        "bra LW%=;\n\t"
        "LD%=:\n\t}"
        :: "r"(m), "r"(ph) : "memory");
}
__device__ __forceinline__ void bulk_g2s(uint32_t dst, const void* src, uint32_t bytes, uint32_t mbar) {
    asm volatile("cp.async.bulk.shared::cluster.global.mbarrier::complete_tx::bytes [%0], [%1], %2, [%3];"
                 :: "r"(dst), "l"(src), "r"(bytes), "r"(mbar) : "memory");
}
__device__ __forceinline__ void mma16816(float d[4], const uint32_t a[4], uint32_t b0, uint32_t b1) {
    asm volatile("mma.sync.aligned.m16n8k16.row.col.f32.f16.f16.f32 "
                 "{%0,%1,%2,%3}, {%4,%5,%6,%7}, {%8,%9}, {%0,%1,%2,%3};"
                 : "+f"(d[0]), "+f"(d[1]), "+f"(d[2]), "+f"(d[3])
                 : "r"(a[0]), "r"(a[1]), "r"(a[2]), "r"(a[3]), "r"(b0), "r"(b1));
}
__device__ __forceinline__ void ldsm4(uint32_t r[4], uint32_t addr) {
    asm volatile("ldmatrix.sync.aligned.m8n8.x4.shared.b16 {%0,%1,%2,%3}, [%4];"
                 : "=r"(r[0]), "=r"(r[1]), "=r"(r[2]), "=r"(r[3]) : "r"(addr));
}

// ---------------- prep kernels ----------------
__global__ void __launch_bounds__(1024) prep_mask_kernel(const float* __restrict__ mm) {
    __shared__ int wcnt[32], woff[33];
    int t = threadIdx.x, w = t >> 5, lane = t & 31, b = t >> 8;
    int act = (mm[t] != 0.f);
    unsigned bal = __ballot_sync(0xffffffffu, act);
    if (lane == 0) wcnt[w] = __popc(bal);
    __syncthreads();
    if (t == 0) {
        int s = 0;
        for (int q = 0; q < 32; q++) { woff[q] = s; s += wcnt[q]; }
        woff[32] = s; g_total = s;
        for (int bb = 0; bb < 4; bb++) g_jcnt[bb] = woff[bb * 8 + 8] - woff[bb * 8];
    }
    __syncthreads();
    if (act) {
        int pg = woff[w] + __popc(bal & ((1u << lane) - 1u));
        g_jlist[b * Nn + (pg - woff[b * 8])] = t & 255;
        g_gilist[pg] = t;
        g_slot[t] = pg;
    }
}

// W2T: 16 chunks of [k=256 rows x 64B (32 h halves)], row-swizzled by ((k>>1)&3)<<4.
__global__ void __launch_bounds__(256) prep_w2t_kernel(const float* __restrict__ W2) {
    int idx = blockIdx.x * 256 + threadIdx.x;   // 16 * 256 * 16 = 65536
    int hc2 = idx >> 12;            // 0..15
    int rem = idx & 4095;
    int k   = rem >> 4;             // 0..255
    int hp  = (rem & 15) * 2;       // 0,2,..,30 (h rel)
    int h   = hc2 * 32 + hp;
    __half2 v = __floats2half2_rn(W2[h * Kk + k], W2[(h + 1) * Kk + k]);
    uint32_t byt = (uint32_t)hc2 * 16384u + (uint32_t)k * 64u
                 + (((uint32_t)hp * 2u) ^ ((((uint32_t)k >> 1) & 3u) << 4));
    *(__half2*)((char*)g_w2t + byt) = v;
}

// TMP[slot][h][c] = sum_a z[gilist[slot]][a] * W1[(a*32+c)*512 + h]; fc-outer (W1 loaded 4x not 16x).
#define PT_ZS   0
#define PT_W1S  8448
#define PT_STG  41728
#define PT_SMEM 205568
__global__ void __launch_bounds__(256) prep_tmp_kernel(const float* __restrict__ z,
                                                       const float* __restrict__ W1) {
    extern __shared__ char psm[];
    float* zs  = (float*)(psm + PT_ZS);     // [64][33]
    float* W1s = (float*)(psm + PT_W1S);    // [32][260]
    char*  stg = psm + PT_STG;              // [64 slots][32 h][80B pitch]
    __shared__ int giS[64];

    const int total = g_total;
    int it = blockIdx.x;
    if (it * 64 >= total) return;
    int ht = blockIdx.y, t = threadIdx.x;
    int c8 = t >> 5, hl = t & 31;

    if (t < 64) giS[t] = (it * 64 + t < total) ? g_gilist[it * 64 + t] : -1;
    __syncthreads();

    for (int idx = t; idx < 64 * 32; idx += 256) {
        int r = idx >> 5, a = idx & 31;
        zs[r * 33 + a] = (giS[r] >= 0) ? z[giS[r] * Dd + a] : 0.f;
    }

    for (int fc = 0; fc < 4; fc++) {
        __syncthreads();
        {
            int c = fc * 8 + c8, h = ht * 32 + hl;
            #pragma unroll
            for (int a = 0; a < 32; a++)
                W1s[a * 260 + t] = W1[(a * Dd + c) * Hh + h];
        }
        __syncthreads();
        int c = fc * 8 + c8;
        #pragma unroll
        for (int ig = 0; ig < 4; ig++) {
            float acc[16];
            #pragma unroll
            for (int ii = 0; ii < 16; ii++) acc[ii] = 0.f;
            #pragma unroll 8
            for (int a = 0; a < 32; a++) {
                float w = W1s[a * 260 + t];
                #pragma unroll
                for (int ii = 0; ii < 16; ii++)
                    acc[ii] += w * zs[(ig * 16 + ii) * 33 + a];
            }
            #pragma unroll
            for (int ii = 0; ii < 16; ii++)
                *(__half*)(stg + (ig * 16 + ii) * 2560 + hl * 80 + c * 2) = __float2half(acc[ii]);
        }
    }
    __syncthreads();
    // coalesced store: 8192 uint4
    #pragma unroll
    for (int q = 0; q < 32; q++) {
        int idx = t + 256 * q;
        int sl = idx >> 7, h_l = (idx >> 2) & 31, qt = idx & 3;
        int s = it * 64 + sl;
        if (s < total) {
            uint4 v = *(const uint4*)(stg + sl * 2560 + h_l * 80 + qt * 16);
            *(uint4*)((char*)g_tmph + (size_t)s * 32768 + (ht * 32 + h_l) * 64 + qt * 16) = v;
        }
    }
}

// ---------------- main kernel ----------------
// dyn smem: zjS 4K @0 | tmpS 32K @4096 | W2 2x16K @36864 | h1 8K @69632  = 77824
#define ZJ_OFF  0
#define TMP_OFF 4096
#define W2_OFF  36864
#define H1_OFF  69632
#define MAIN_SMEM 77824

__global__ void __launch_bounds__(256, 2)
decoder_hmma_kernel(const float* __restrict__ z, const float* __restrict__ mm,
                    const float* __restrict__ b1, const float* __restrict__ b2,
                    const float* __restrict__ W3, const float* __restrict__ b3,
                    float* __restrict__ out)
{
    extern __shared__ char dsm[];
    __shared__ float b1s[512], b2s[256], w3s[256], mmS[256], part[64];
    __shared__ int jlS[256];
    __shared__ __align__(8) uint64_t mbars[2];

    const int t    = threadIdx.x;
    const int w    = t >> 5;
    const int lane = t & 31;
    const int wr   = w >> 2;
    const int wc   = w & 3;
    const int lr   = lane >> 2;
    const int lc   = (lane & 3) * 2;
    const int mrow = lane & 7;
    const int mg   = lane >> 3;

    const int bi = blockIdx.x;
    const int b  = bi >> 8;
    const int i  = bi & 255;

    const uint32_t smb = s2u(dsm);
    const uint32_t mb0 = s2u(mbars);

    for (int k = t; k < 512; k += 256) b1s[k] = b1[k];
    b2s[t] = b2[t];
    w3s[t] = W3[t]; mmS[t] = mm[b * Nn + t]; jlS[t] = g_jlist[b * Nn + t];
    __syncthreads();

    const float mi = mmS[i];
    if (mi == 0.f || mmS[t] == 0.f) {
        size_t o = (size_t)bi * Nn + t;
        out[o] = 0.5f;
        out[(size_t)Bb * Nn * Nn + o] = 0.f;
    }
    if (mi == 0.f) return;

    const int sg     = g_slot[bi];
    const int Kact   = g_jcnt[b];
    const int ntiles = (Kact + 63) >> 6;
    const int totalq = ntiles * 16;

    {   // tmpS: 512 rows x 64B, swizzled by ((row>>1)&3)<<4 per 16B chunk
        const char* gsrc = (const char*)g_tmph + (size_t)sg * 32768;
        #pragma unroll
        for (int r8 = 0; r8 < 8; r8++) {
            int idx = t + 256 * r8;
            int row = idx >> 2, q = idx & 3;
            uint4 v = *(const uint4*)(gsrc + row * 64 + q * 16);
            *(uint4*)(dsm + TMP_OFF + row * 64 + ((q * 16) ^ (((row >> 1) & 3) << 4))) = v;
        }
    }
    if (t == 0) { mbar_init(mb0, 1); mbar_init(mb0 + 8, 1); }
    __syncthreads();
    if (t == 0) {                       // initial: chunk 0 -> buf0
        mbar_expect(mb0, 16384);
        bulk_g2s(smb + W2_OFF, (const char*)g_w2t, 16384, mb0);
    }

    const float b3v = b3[0];
    const char* h1p = dsm + H1_OFF;
    const uint32_t h1b = smb + H1_OFF;

    for (int jt = 0; jt < ntiles; jt++) {
        // per-tile zjS fill (64 rows x 64B, swizzled like tmpS) + part zero
        if (t < 64) {
            part[t] = 0.f;
            int idx = jt * 64 + t;
            char* zr = dsm + ZJ_OFF + t * 64;
            uint32_t sw = (((uint32_t)t >> 1) & 3u) << 4;
            if (idx < Kact) {
                const float4* zp = (const float4*)(z + ((size_t)b * Nn + jlS[idx]) * Dd);
                #pragma unroll
                for (int c4 = 0; c4 < 8; c4++) {
                    float4 v = zp[c4];
                    *(__half2*)(zr + (((uint32_t)(c4 * 8))     ^ sw)) = __floats2half2_rn(v.x, v.y);
                    *(__half2*)(zr + (((uint32_t)(c4 * 8 + 4)) ^ sw)) = __floats2half2_rn(v.z, v.w);
                }
            } else {
                #pragma unroll
                for (int c4 = 0; c4 < 8; c4++) {
                    *(__half2*)(zr + (((uint32_t)(c4 * 8))     ^ sw)) = __floats2half2_rn(0.f, 0.f);
                    *(__half2*)(zr + (((uint32_t)(c4 * 8 + 4)) ^ sw)) = __floats2half2_rn(0.f, 0.f);
                }
            }
        }
        __syncthreads();

        float acc2[2][8][4];
        #pragma unroll
        for (int mt = 0; mt < 2; mt++)
            #pragma unroll
            for (int nt = 0; nt < 8; nt++)
                #pragma unroll
                for (int e = 0; e < 4; e++) acc2[mt][nt][e] = 0.f;

        for (int hc = 0; hc < 8; hc++) {
            const int g  = (jt * 8 + hc);     // 64h-group index (global)
            const int q0 = g * 2;             // even 16KB chunk
            const int q1 = q0 + 1;            // odd 16KB chunk

            // ---- MMA1 (64h) into regs ----
            float acc1[2][2][4];
            #pragma unroll
            for (int mt = 0; mt < 2; mt++)
                #pragma unroll
                for (int nt = 0; nt < 2; nt++)
                    #pragma unroll
                    for (int e = 0; e < 4; e++) acc1[mt][nt][e] = 0.f;

            #pragma unroll
            for (int kk = 0; kk < 2; kk++) {
                const uint32_t cb = (uint32_t)((kk * 16 + (mg >> 1) * 8) * 2);
                uint32_t bf[4];
                {
                    int nh = hc * 64 + wc * 16 + (mg & 1) * 8 + mrow;
                    ldsm4(bf, smb + TMP_OFF + (uint32_t)nh * 64u + (cb ^ ((((uint32_t)nh >> 1) & 3u) << 4)));
                }
                #pragma unroll
                for (int mt = 0; mt < 2; mt++) {
                    uint32_t af[4];
                    int jr = wr * 32 + mt * 16 + (mg & 1) * 8 + mrow;
                    ldsm4(af, smb + ZJ_OFF + (uint32_t)jr * 64u + (cb ^ ((((uint32_t)jr >> 1) & 3u) << 4)));
                    mma16816(acc1[mt][0], af, bf[0], bf[2]);
                    mma16816(acc1[mt][1], af, bf[1], bf[3]);
                }
            }

            __syncthreads();   // syncA: prev group's MMA2-B h1 reads done; buf1 free
            if (t == 0 && q1 < totalq) {
                mbar_expect(mb0 + 8, 16384);
                bulk_g2s(smb + W2_OFF + 16384, (const char*)g_w2t + (q1 & 15) * 16384, 16384, mb0 + 8);
            }

            // ---- h1 store (64 rows x 128B, swizzled by (row&7)<<4) ----
            #pragma unroll
            for (int mt = 0; mt < 2; mt++)
                #pragma unroll
                for (int nt = 0; nt < 2; nt++) {
                    int rl = wr * 32 + mt * 16 + lr;
                    int hl = wc * 16 + nt * 8 + lc;
                    int hg = hc * 64 + hl;
                    uint32_t sw = ((uint32_t)rl & 7u) << 4;
                    float v0 = fmaxf(acc1[mt][nt][0] + b1s[hg],     0.f);
                    float v1 = fmaxf(acc1[mt][nt][1] + b1s[hg + 1], 0.f);
                    float v2 = fmaxf(acc1[mt][nt][2] + b1s[hg],     0.f);
                    float v3 = fmaxf(acc1[mt][nt][3] + b1s[hg + 1], 0.f);
                    *(__half2*)(h1p + rl * 128 + (((uint32_t)(hl * 2)) ^ sw))       = __floats2half2_rn(v0, v1);
                    *(__half2*)(h1p + (rl + 8) * 128 + (((uint32_t)(hl * 2)) ^ sw)) = __floats2half2_rn(v2, v3);
                }

            mbar_wait(mb0, (q0 >> 1) & 1);
            __syncthreads();   // syncH1: h1 visible, buf0 chunk q0 ready

            // ---- MMA2 half A (h 0..31 of group, chunk q0 in buf0) ----
            #pragma unroll
            for (int kk = 0; kk < 2; kk++) {
                const uint32_t kb = (uint32_t)((kk * 16 + (mg >> 1) * 8) * 2);
                uint32_t bfs[4][4];
                #pragma unroll
                for (int p = 0; p < 4; p++) {
                    int n = wc * 64 + p * 16 + (mg & 1) * 8 + mrow;
                    ldsm4(bfs[p], smb + W2_OFF + (uint32_t)n * 64u + (kb ^ ((((uint32_t)n >> 1) & 3u) << 4)));
                }
                #pragma unroll
                for (int mt = 0; mt < 2; mt++) {
                    uint32_t af[4];
                    int rl = wr * 32 + mt * 16 + (mg & 1) * 8 + mrow;
                    ldsm4(af, h1b + (uint32_t)rl * 128u + (kb ^ (((uint32_t)rl & 7u) << 4)));
                    #pragma unroll
                    for (int p = 0; p < 4; p++) {
                        mma16816(acc2[mt][2 * p],     af, bfs[p][0], bfs[p][2]);
                        mma16816(acc2[mt][2 * p + 1], af, bfs[p][1], bfs[p][3]);
                    }
                }
            }

            __syncthreads();   // syncC: buf0 reads done
            if (t == 0 && q0 + 2 < totalq) {
                mbar_expect(mb0, 16384);
                bulk_g2s(smb + W2_OFF, (const char*)g_w2t + ((q0 + 2) & 15) * 16384, 16384, mb0);
            }
            mbar_wait(mb0 + 8, (q1 >> 1) & 1);

            // ---- MMA2 half B (h 32..63 of group, chunk q1 in buf1) ----
            #pragma unroll
            for (int kk = 0; kk < 2; kk++) {
                const uint32_t kb  = (uint32_t)((kk * 16 + (mg >> 1) * 8) * 2);
                const uint32_t ccb = kb + 64u;      // h1 column offset for upper 32 h
                uint32_t bfs[4][4];
                #pragma unroll
                for (int p = 0; p < 4; p++) {
                    int n = wc * 64 + p * 16 + (mg & 1) * 8 + mrow;
                    ldsm4(bfs[p], smb + W2_OFF + 16384u + (uint32_t)n * 64u + (kb ^ ((((uint32_t)n >> 1) & 3u) << 4)));
                }
                #pragma unroll
                for (int mt = 0; mt < 2; mt++) {
                    uint32_t af[4];
                    int rl = wr * 32 + mt * 16 + (mg & 1) * 8 + mrow;
                    ldsm4(af, h1b + (uint32_t)rl * 128u + (ccb ^ (((uint32_t)rl & 7u) << 4)));
                    #pragma unroll
                    for (int p = 0; p < 4; p++) {
                        mma16816(acc2[mt][2 * p],     af, bfs[p][0], bfs[p][2]);
                        mma16816(acc2[mt][2 * p + 1], af, bfs[p][1], bfs[p][3]);
                    }
                }
            }
        }

        // ---- epilogue ----
        float s[2][2] = {{0.f, 0.f}, {0.f, 0.f}};
        #pragma unroll
        for (int mt = 0; mt < 2; mt++)
            #pragma unroll
            for (int nt = 0; nt < 8; nt++) {
                int k = wc * 64 + nt * 8 + lc;
                s[mt][0] += fmaxf(acc2[mt][nt][0] + b2s[k],     0.f) * w3s[k]
                          + fmaxf(acc2[mt][nt][1] + b2s[k + 1], 0.f) * w3s[k + 1];
                s[mt][1] += fmaxf(acc2[mt][nt][2] + b2s[k],     0.f) * w3s[k]
                          + fmaxf(acc2[mt][nt][3] + b2s[k + 1], 0.f) * w3s[k + 1];
            }
        #pragma unroll
        for (int off = 1; off <= 2; off <<= 1) {
            #pragma unroll
            for (int mt = 0; mt < 2; mt++) {
                s[mt][0] += __shfl_xor_sync(0xffffffffu, s[mt][0], off);
                s[mt][1] += __shfl_xor_sync(0xffffffffu, s[mt][1], off);
            }
        }
        if ((lane & 3) == 0) {
            #pragma unroll
            for (int mt = 0; mt < 2; mt++) {
                int r0 = wr * 32 + mt * 16 + lr;
                atomicAdd(&part[r0],     s[mt][0]);
                atomicAdd(&part[r0 + 8], s[mt][1]);
            }
        }
        __syncthreads();
        if (t < 64) {
            int idx = jt * 64 + t;
            if (idx < Kact) {
                int j = jlS[idx];
                float lg = part[t] + b3v;
                size_t o = (size_t)bi * Nn + j;
                out[o] = 1.f / (1.f + __expf(-lg));
                out[(size_t)Bb * Nn * Nn + o] = lg;
            }
        }
        __syncthreads();
    }
}

extern "C" void kernel_launch(void* const* d_in, const int* in_sizes, int n_in,
                              void* d_out, int out_size)
{
    const float* z   = (const float*)d_in[0];
    const float* mmk = (const float*)d_in[1];
    const float* W1  = (const float*)d_in[3];
    const float* b1  = (const float*)d_in[4];
    const float* W2  = (const float*)d_in[5];
    const float* b2  = (const float*)d_in[6];
    const float* W3  = (const float*)d_in[7];
    const float* b3  = (const float*)d_in[8];
    float* out = (float*)d_out;

    cudaFuncSetAttribute(decoder_hmma_kernel,
                         cudaFuncAttributeMaxDynamicSharedMemorySize, MAIN_SMEM);
    cudaFuncSetAttribute(prep_tmp_kernel,
                         cudaFuncAttributeMaxDynamicSharedMemorySize, PT_SMEM);

    prep_mask_kernel<<<1, 1024>>>(mmk);
    prep_w2t_kernel<<<256, 256>>>(W2);
    prep_tmp_kernel<<<dim3(16, 16), 256, PT_SMEM>>>(z, W1);
    decoder_hmma_kernel<<<Bb * Nn, 256, MAIN_SMEM>>>(z, mmk, b1, b2, W3, b3, out);
}

// round 9
// speedup vs baseline: 1.3895x; 1.0015x over previous
#include <cuda_runtime.h>
#include <cuda_fp16.h>
#include <stdint.h>

#define Bb 4
#define Nn 256
#define Dd 32
#define Hh 512
#define Kk 256
#define GRID_MAIN 296

// device scratch
__device__ uint4 g_tmph[((size_t)Bb*Nn*Hh*Dd*2)/16];   // fp16 TMP per SLOT [s][h 512][c 32]
__device__ uint4 g_w2t [(16*Kk*64)/16];                 // 256 KB fp16 W2^T: 16 chunks [k 256 x 32h]
__device__ int   g_jlist[Bb*Nn];
__device__ int   g_jcnt[Bb];
__device__ int   g_gilist[Bb*Nn];
__device__ int   g_slot[Bb*Nn];
__device__ int   g_total;
__device__ int   g_unit[Bb*Nn*4];                       // (slot<<4)|jt, grouped by slot
__device__ int   g_U;

// ---------------- helpers ----------------
__device__ __forceinline__ uint32_t s2u(const void* p) {
    uint32_t a;
    asm("{ .reg .u64 t; cvta.to.shared.u64 t, %1; cvt.u32.u64 %0, t; }" : "=r"(a) : "l"(p));
    return a;
}
__device__ __forceinline__ void mbar_init(uint32_t m, uint32_t c) {
    asm volatile("mbarrier.init.shared.b64 [%0], %1;" :: "r"(m), "r"(c) : "memory");
}
__device__ __forceinline__ void mbar_expect(uint32_t m, uint32_t bytes) {
    asm volatile("mbarrier.arrive.expect_tx.shared.b64 _, [%0], %1;" :: "r"(m), "r"(bytes) : "memory");
}
__device__ __forceinline__ void mbar_wait(uint32_t m, uint32_t ph) {
    asm volatile(
        "{\n\t.reg .pred P;\n\t"
        "LW%=:\n\t"
        "mbarrier.try_wait.parity.shared.b64 P, [%0], %1, 0x989680;\n\t"
        "@P bra LD%=;\n\t"
        "bra LW%=;\n\t"
        "LD%=:\n\t}"
        :: "r"(m), "r"(ph) : "memory");
}
__device__ __forceinline__ void bulk_g2s(uint32_t dst, const void* src, uint32_t bytes, uint32_t mbar) {
    asm volatile("cp.async.bulk.shared::cluster.global.mbarrier::complete_tx::bytes [%0], [%1], %2, [%3];"
                 :: "r"(dst), "l"(src), "r"(bytes), "r"(mbar) : "memory");
}
__device__ __forceinline__ void mma16816(float d[4], const uint32_t a[4], uint32_t b0, uint32_t b1) {
    asm volatile("mma.sync.aligned.m16n8k16.row.col.f32.f16.f16.f32 "
                 "{%0,%1,%2,%3}, {%4,%5,%6,%7}, {%8,%9}, {%0,%1,%2,%3};"
                 : "+f"(d[0]), "+f"(d[1]), "+f"(d[2]), "+f"(d[3])
                 : "r"(a[0]), "r"(a[1]), "r"(a[2]), "r"(a[3]), "r"(b0), "r"(b1));
}
__device__ __forceinline__ void ldsm4(uint32_t r[4], uint32_t addr) {
    asm volatile("ldmatrix.sync.aligned.m8n8.x4.shared.b16 {%0,%1,%2,%3}, [%4];"
                 : "=r"(r[0]), "=r"(r[1]), "=r"(r[2]), "=r"(r[3]) : "r"(addr));
}

// ---------------- prep kernels ----------------
__global__ void __launch_bounds__(256) out_init_kernel(float* __restrict__ out) {
    int idx = blockIdx.x * 256 + threadIdx.x;     // 131072 float4
    float4* o4 = (float4*)out;
    float v = (idx < 65536) ? 0.5f : 0.f;
    o4[idx] = make_float4(v, v, v, v);
}

__global__ void __launch_bounds__(1024) prep_mask_kernel(const float* __restrict__ mm) {
    __shared__ int wcnt[32], woff[33];
    __shared__ int ubase[4], sbase[4], ntl[4];
    int t = threadIdx.x, w = t >> 5, lane = t & 31, b = t >> 8;
    int act = (mm[t] != 0.f);
    unsigned bal = __ballot_sync(0xffffffffu, act);
    if (lane == 0) wcnt[w] = __popc(bal);
    __syncthreads();
    if (t == 0) {
        int s = 0;
        for (int q = 0; q < 32; q++) { woff[q] = s; s += wcnt[q]; }
        woff[32] = s; g_total = s;
        int ub = 0;
        for (int bb = 0; bb < 4; bb++) {
            int jc = woff[bb * 8 + 8] - woff[bb * 8];
            g_jcnt[bb] = jc;
            sbase[bb] = woff[bb * 8];
            int nt = (jc + 63) >> 6;
            ntl[bb] = nt;
            ubase[bb] = ub;
            ub += jc * nt;
        }
        g_U = ub;
    }
    __syncthreads();
    if (act) {
        int pg = woff[w] + __popc(bal & ((1u << lane) - 1u));
        g_jlist[b * Nn + (pg - woff[b * 8])] = t & 255;
        g_gilist[pg] = t;
        g_slot[t] = pg;
        int nt = ntl[b];
        int ub = ubase[b] + (pg - sbase[b]) * nt;
        for (int jt = 0; jt < nt; jt++) g_unit[ub + jt] = (pg << 4) | jt;
    }
}

// W2T: 16 chunks of [k=256 rows x 64B (32 h halves)], row-swizzled by ((k>>1)&3)<<4.
__global__ void __launch_bounds__(256) prep_w2t_kernel(const float* __restrict__ W2) {
    int idx = blockIdx.x * 256 + threadIdx.x;   // 65536
    int hc2 = idx >> 12;
    int rem = idx & 4095;
    int k   = rem >> 4;
    int hp  = (rem & 15) * 2;
    int h   = hc2 * 32 + hp;
    __half2 v = __floats2half2_rn(W2[h * Kk + k], W2[(h + 1) * Kk + k]);
    uint32_t byt = (uint32_t)hc2 * 16384u + (uint32_t)k * 64u
                 + (((uint32_t)hp * 2u) ^ ((((uint32_t)k >> 1) & 3u) << 4));
    *(__half2*)((char*)g_w2t + byt) = v;
}

// TMP[slot][h][c] = sum_a z[gilist[slot]][a] * W1[(a*32+c)*512 + h]
#define PT_ZS   0
#define PT_W1S  8448
#define PT_STG  41728
#define PT_SMEM 205568
__global__ void __launch_bounds__(256) prep_tmp_kernel(const float* __restrict__ z,
                                                       const float* __restrict__ W1) {
    extern __shared__ char psm[];
    float* zs  = (float*)(psm + PT_ZS);
    float* W1s = (float*)(psm + PT_W1S);
    char*  stg = psm + PT_STG;
    __shared__ int giS[64];

    const int total = g_total;
    int it = blockIdx.x;
    if (it * 64 >= total) return;
    int ht = blockIdx.y, t = threadIdx.x;
    int c8 = t >> 5, hl = t & 31;

    if (t < 64) giS[t] = (it * 64 + t < total) ? g_gilist[it * 64 + t] : -1;
    __syncthreads();

    for (int idx = t; idx < 64 * 32; idx += 256) {
        int r = idx >> 5, a = idx & 31;
        zs[r * 33 + a] = (giS[r] >= 0) ? z[giS[r] * Dd + a] : 0.f;
    }

    for (int fc = 0; fc < 4; fc++) {
        __syncthreads();
        {
            int c = fc * 8 + c8, h = ht * 32 + hl;
            #pragma unroll
            for (int a = 0; a < 32; a++)
                W1s[a * 260 + t] = W1[(a * Dd + c) * Hh + h];
        }
        __syncthreads();
        int c = fc * 8 + c8;
        #pragma unroll
        for (int ig = 0; ig < 4; ig++) {
            float acc[16];
            #pragma unroll
            for (int ii = 0; ii < 16; ii++) acc[ii] = 0.f;
            #pragma unroll 8
            for (int a = 0; a < 32; a++) {
                float wv = W1s[a * 260 + t];
                #pragma unroll
                for (int ii = 0; ii < 16; ii++)
                    acc[ii] += wv * zs[(ig * 16 + ii) * 33 + a];
            }
            #pragma unroll
            for (int ii = 0; ii < 16; ii++)
                *(__half*)(stg + (ig * 16 + ii) * 2560 + hl * 80 + c * 2) = __float2half(acc[ii]);
        }
    }
    __syncthreads();
    #pragma unroll
    for (int q = 0; q < 32; q++) {
        int idx = t + 256 * q;
        int sl = idx >> 7, h_l = (idx >> 2) & 31, qt = idx & 3;
        int s = it * 64 + sl;
        if (s < total) {
            uint4 v = *(const uint4*)(stg + sl * 2560 + h_l * 80 + qt * 16);
            *(uint4*)((char*)g_tmph + (size_t)s * 32768 + (ht * 32 + h_l) * 64 + qt * 16) = v;
        }
    }
}

// ---------------- main kernel (persistent) ----------------
// dyn smem: zjS 4K @0 | tmpS 32K @4096 | W2 2x16K @36864 | h1 2x8K @69632 = 86016
#define ZJ_OFF  0
#define TMP_OFF 4096
#define W2_OFF  36864
#define H1_OFF  69632
#define MAIN_SMEM 86016

__global__ void __launch_bounds__(256, 2)
decoder_hmma_kernel(const float* __restrict__ z, const float* __restrict__ b1,
                    const float* __restrict__ b2, const float* __restrict__ W3,
                    const float* __restrict__ b3, float* __restrict__ out)
{
    extern __shared__ char dsm[];
    __shared__ float b1s[512], b2s[256], w3s[256], part[64];
    __shared__ int jlS[256];
    __shared__ __align__(8) uint64_t mbars[2];

    const int t    = threadIdx.x;
    const int w    = t >> 5;
    const int lane = t & 31;
    const int wr   = w >> 2;
    const int wc   = w & 3;
    const int lr   = lane >> 2;
    const int lc   = (lane & 3) * 2;
    const int mrow = lane & 7;
    const int mg   = lane >> 3;

    const int U  = g_U;
    const int u0 = (int)(((long long)blockIdx.x * U) / GRID_MAIN);
    const int u1 = (int)(((long long)(blockIdx.x + 1) * U) / GRID_MAIN);
    if (u0 >= u1) return;

    const uint32_t smb = s2u(dsm);
    const uint32_t mb0 = s2u(mbars);

    for (int k = t; k < 512; k += 256) b1s[k] = b1[k];
    b2s[t] = b2[t];
    w3s[t] = W3[t];
    if (t == 0) { mbar_init(mb0, 1); mbar_init(mb0 + 8, 1); }
    __syncthreads();
    if (t == 0) {                       // first chunk q0 = sub-chunk 0 -> buf0
        mbar_expect(mb0, 16384);
        bulk_g2s(smb + W2_OFF, (const char*)g_w2t, 16384, mb0);
    }

    const float b3v = b3[0];
    const int totalC = (u1 - u0) * 8;
    int C = 0, pw0 = 0, pw1 = 0;
    int bprev = -1, sprev = -1;

    for (int u = u0; u < u1; u++) {
        const int enc = g_unit[u];
        const int s   = enc >> 4;
        const int jt  = enc & 15;
        const int gi  = g_gilist[s];
        const int b   = gi >> 8;

        if (b != bprev) {
            jlS[t] = g_jlist[b * Nn + t];
            bprev = b;
            __syncthreads();
        }
        const int Kact = g_jcnt[b];

        if (s != sprev) {               // tmpS: 512 rows x 64B, swizzle ((row>>1)&3)<<4
            const char* gsrc = (const char*)g_tmph + (size_t)s * 32768;
            #pragma unroll
            for (int r8 = 0; r8 < 8; r8++) {
                int idx = t + 256 * r8;
                int row = idx >> 2, q = idx & 3;
                uint4 v = *(const uint4*)(gsrc + row * 64 + q * 16);
                *(uint4*)(dsm + TMP_OFF + row * 64 + ((q * 16) ^ (((row >> 1) & 3) << 4))) = v;
            }
            sprev = s;
        }

        if (t < 64) {                   // zjS (64 rows x 64B, same swizzle) + part zero
            part[t] = 0.f;
            int idx = jt * 64 + t;
            char* zr = dsm + ZJ_OFF + t * 64;
            uint32_t sw = (((uint32_t)t >> 1) & 3u) << 4;
            if (idx < Kact) {
                const float4* zp = (const float4*)(z + ((size_t)b * Nn + jlS[idx]) * Dd);
                #pragma unroll
                for (int c4 = 0; c4 < 8; c4++) {
                    float4 v = zp[c4];
                    *(__half2*)(zr + (((uint32_t)(c4 * 8))     ^ sw)) = __floats2half2_rn(v.x, v.y);
                    *(__half2*)(zr + (((uint32_t)(c4 * 8 + 4)) ^ sw)) = __floats2half2_rn(v.z, v.w);
                }
            } else {
                #pragma unroll
                for (int c4 = 0; c4 < 8; c4++) {
                    *(__half2*)(zr + (((uint32_t)(c4 * 8))     ^ sw)) = __floats2half2_rn(0.f, 0.f);
                    *(__half2*)(zr + (((uint32_t)(c4 * 8 + 4)) ^ sw)) = __floats2half2_rn(0.f, 0.f);
                }
            }
        }
        __syncthreads();

        float acc2[2][8][4];
        #pragma unroll
        for (int mt = 0; mt < 2; mt++)
            #pragma unroll
            for (int nt = 0; nt < 8; nt++)
                #pragma unroll
                for (int e = 0; e < 4; e++) acc2[mt][nt][e] = 0.f;

        for (int hc = 0; hc < 8; hc++) {
            // ---- MMA1 (64h) into regs ----
            float acc1[2][2][4];
            #pragma unroll
            for (int mt = 0; mt < 2; mt++)
                #pragma unroll
                for (int nt = 0; nt < 2; nt++)
                    #pragma unroll
                    for (int e = 0; e < 4; e++) acc1[mt][nt][e] = 0.f;

            #pragma unroll
            for (int kk = 0; kk < 2; kk++) {
                const uint32_t cb = (uint32_t)((kk * 16 + (mg >> 1) * 8) * 2);
                uint32_t bf[4];
                {
                    int nh = hc * 64 + wc * 16 + (mg & 1) * 8 + mrow;
                    ldsm4(bf, smb + TMP_OFF + (uint32_t)nh * 64u + (cb ^ ((((uint32_t)nh >> 1) & 3u) << 4)));
                }
                #pragma unroll
                for (int mt = 0; mt < 2; mt++) {
                    uint32_t af[4];
                    int jr = wr * 32 + mt * 16 + (mg & 1) * 8 + mrow;
                    ldsm4(af, smb + ZJ_OFF + (uint32_t)jr * 64u + (cb ^ ((((uint32_t)jr >> 1) & 3u) << 4)));
                    mma16816(acc1[mt][0], af, bf[0], bf[2]);
                    mma16816(acc1[mt][1], af, bf[1], bf[3]);
                }
            }

            // ---- h1 store into double buffer C&1 (no barrier needed before) ----
            char* h1p = dsm + H1_OFF + (C & 1) * 8192;
            const uint32_t h1b = smb + H1_OFF + (uint32_t)(C & 1) * 8192u;
            #pragma unroll
            for (int mt = 0; mt < 2; mt++)
                #pragma unroll
                for (int nt = 0; nt < 2; nt++) {
                    int rl = wr * 32 + mt * 16 + lr;
                    int hl = wc * 16 + nt * 8 + lc;
                    int hg = hc * 64 + hl;
                    uint32_t sw = ((uint32_t)rl & 7u) << 4;
                    float v0 = fmaxf(acc1[mt][nt][0] + b1s[hg],     0.f);
                    float v1 = fmaxf(acc1[mt][nt][1] + b1s[hg + 1], 0.f);
                    float v2 = fmaxf(acc1[mt][nt][2] + b1s[hg],     0.f);
                    float v3 = fmaxf(acc1[mt][nt][3] + b1s[hg + 1], 0.f);
                    *(__half2*)(h1p + rl * 128 + (((uint32_t)(hl * 2)) ^ sw))       = __floats2half2_rn(v0, v1);
                    *(__half2*)(h1p + (rl + 8) * 128 + (((uint32_t)(hl * 2)) ^ sw)) = __floats2half2_rn(v2, v3);
                }

            mbar_wait(mb0, pw0 & 1); pw0++;
            __syncthreads();    // h1 visible + buf0 ready for all

            if (t == 0) {       // buf1 <- sub-chunk 2C+1 (prev readers passed barrier)
                mbar_expect(mb0 + 8, 16384);
                bulk_g2s(smb + W2_OFF + 16384,
                         (const char*)g_w2t + ((2 * C + 1) & 15) * 16384, 16384, mb0 + 8);
            }

            // ---- MMA2 half A (W2 buf0) ----
            #pragma unroll
            for (int kk = 0; kk < 2; kk++) {
                const uint32_t kb = (uint32_t)((kk * 16 + (mg >> 1) * 8) * 2);
                uint32_t bfs[4][4];
                #pragma unroll
                for (int p = 0; p < 4; p++) {
                    int n = wc * 64 + p * 16 + (mg & 1) * 8 + mrow;
                    ldsm4(bfs[p], smb + W2_OFF + (uint32_t)n * 64u + (kb ^ ((((uint32_t)n >> 1) & 3u) << 4)));
                }
                #pragma unroll
                for (int mt = 0; mt < 2; mt++) {
                    uint32_t af[4];
                    int rl = wr * 32 + mt * 16 + (mg & 1) * 8 + mrow;
                    ldsm4(af, h1b + (uint32_t)rl * 128u + (kb ^ (((uint32_t)rl & 7u) << 4)));
                    #pragma unroll
                    for (int p = 0; p < 4; p++) {
                        mma16816(acc2[mt][2 * p],     af, bfs[p][0], bfs[p][2]);
                        mma16816(acc2[mt][2 * p + 1], af, bfs[p][1], bfs[p][3]);
                    }
                }
            }

            __syncthreads();    // buf0 reads done
            if (t == 0 && C + 1 < totalC) {   // buf0 <- next chunk's even sub-chunk
                mbar_expect(mb0, 16384);
                bulk_g2s(smb + W2_OFF,
                         (const char*)g_w2t + ((2 * C + 2) & 15) * 16384, 16384, mb0);
            }
            mbar_wait(mb0 + 8, pw1 & 1); pw1++;

            // ---- MMA2 half B (W2 buf1, h1 upper 32 h) ----
            #pragma unroll
            for (int kk = 0; kk < 2; kk++) {
                const uint32_t kb  = (uint32_t)((kk * 16 + (mg >> 1) * 8) * 2);
                const uint32_t ccb = kb + 64u;
                uint32_t bfs[4][4];
                #pragma unroll
                for (int p = 0; p < 4; p++) {
                    int n = wc * 64 + p * 16 + (mg & 1) * 8 + mrow;
                    ldsm4(bfs[p], smb + W2_OFF + 16384u + (uint32_t)n * 64u + (kb ^ ((((uint32_t)n >> 1) & 3u) << 4)));
                }
                #pragma unroll
                for (int mt = 0; mt < 2; mt++) {
                    uint32_t af[4];
                    int rl = wr * 32 + mt * 16 + (mg & 1) * 8 + mrow;
                    ldsm4(af, h1b + (uint32_t)rl * 128u + (ccb ^ (((uint32_t)rl & 7u) << 4)));
                    #pragma unroll
                    for (int p = 0; p < 4; p++) {
                        mma16816(acc2[mt][2 * p],     af, bfs[p][0], bfs[p][2]);
                        mma16816(acc2[mt][2 * p + 1], af, bfs[p][1], bfs[p][3]);
                    }
                }
            }
            C++;
        }

        // ---- epilogue ----
        float sacc[2][2] = {{0.f, 0.f}, {0.f, 0.f}};
        #pragma unroll
        for (int mt = 0; mt < 2; mt++)
            #pragma unroll
            for (int nt = 0; nt < 8; nt++) {
                int k = wc * 64 + nt * 8 + lc;
                sacc[mt][0] += fmaxf(acc2[mt][nt][0] + b2s[k],     0.f) * w3s[k]
                             + fmaxf(acc2[mt][nt][1] + b2s[k + 1], 0.f) * w3s[k + 1];
                sacc[mt][1] += fmaxf(acc2[mt][nt][2] + b2s[k],     0.f) * w3s[k]
                             + fmaxf(acc2[mt][nt][3] + b2s[k + 1], 0.f) * w3s[k + 1];
            }
        #pragma unroll
        for (int off = 1; off <= 2; off <<= 1) {
            #pragma unroll
            for (int mt = 0; mt < 2; mt++) {
                sacc[mt][0] += __shfl_xor_sync(0xffffffffu, sacc[mt][0], off);
                sacc[mt][1] += __shfl_xor_sync(0xffffffffu, sacc[mt][1], off);
            }
        }
        if ((lane & 3) == 0) {
            #pragma unroll
            for (int mt = 0; mt < 2; mt++) {
                int r0 = wr * 32 + mt * 16 + lr;
                atomicAdd(&part[r0],     sacc[mt][0]);
                atomicAdd(&part[r0 + 8], sacc[mt][1]);
            }
        }
        __syncthreads();
        if (t < 64) {
            int idx = jt * 64 + t;
            if (idx < Kact) {
                int j = jlS[idx];
                float lg = part[t] + b3v;
                size_t o = (size_t)gi * Nn + j;
                out[o] = 1.f / (1.f + __expf(-lg));
                out[(size_t)Bb * Nn * Nn + o] = lg;
            }
        }
        __syncthreads();
    }
}

extern "C" void kernel_launch(void* const* d_in, const int* in_sizes, int n_in,
                              void* d_out, int out_size)
{
    const float* z   = (const float*)d_in[0];
    const float* mmk = (const float*)d_in[1];
    const float* W1  = (const float*)d_in[3];
    const float* b1  = (const float*)d_in[4];
    const float* W2  = (const float*)d_in[5];
    const float* b2  = (const float*)d_in[6];
    const float* W3  = (const float*)d_in[7];
    const float* b3  = (const float*)d_in[8];
    float* out = (float*)d_out;

    cudaFuncSetAttribute(decoder_hmma_kernel,
                         cudaFuncAttributeMaxDynamicSharedMemorySize, MAIN_SMEM);
    cudaFuncSetAttribute(prep_tmp_kernel,
                         cudaFuncAttributeMaxDynamicSharedMemorySize, PT_SMEM);

    out_init_kernel<<<512, 256>>>(out);
    prep_mask_kernel<<<1, 1024>>>(mmk);
    prep_w2t_kernel<<<256, 256>>>(W2);
    prep_tmp_kernel<<<dim3(16, 16), 256, PT_SMEM>>>(z, W1);
    decoder_hmma_kernel<<<GRID_MAIN, 256, MAIN_SMEM>>>(z, b1, b2, W3, b3, out);
}

// round 10
// speedup vs baseline: 1.5067x; 1.0844x over previous
#include <cuda_runtime.h>
#include <cuda_fp16.h>
#include <stdint.h>

#define Bb 4
#define Nn 256
#define Dd 32
#define Hh 512
#define Kk 256
#define GRID_MAIN 296

// device scratch
__device__ uint4 g_tmph[((size_t)Bb*Nn*Hh*Dd*2)/16];   // fp16 TMP per SLOT [s][h 512][c 32]
__device__ uint4 g_w2t [(16*Kk*64)/16];                 // 256 KB fp16 W2^T: 16 chunks [k 256 x 32h]
__device__ int   g_jlist[Bb*Nn];
__device__ int   g_jcnt[Bb];
__device__ int   g_gilist[Bb*Nn];
__device__ int   g_slot[Bb*Nn];
__device__ int   g_total;
__device__ int   g_unit[Bb*Nn*4];                       // (slot<<4)|jt, grouped by slot
__device__ int   g_U;

// ---------------- helpers ----------------
__device__ __forceinline__ uint32_t s2u(const void* p) {
    uint32_t a;
    asm("{ .reg .u64 t; cvta.to.shared.u64 t, %1; cvt.u32.u64 %0, t; }" : "=r"(a) : "l"(p));
    return a;
}
__device__ __forceinline__ void mbar_init(uint32_t m, uint32_t c) {
    asm volatile("mbarrier.init.shared.b64 [%0], %1;" :: "r"(m), "r"(c) : "memory");
}
__device__ __forceinline__ void mbar_expect(uint32_t m, uint32_t bytes) {
    asm volatile("mbarrier.arrive.expect_tx.shared.b64 _, [%0], %1;" :: "r"(m), "r"(bytes) : "memory");
}
__device__ __forceinline__ void mbar_wait(uint32_t m, uint32_t ph) {
    asm volatile(
        "{\n\t.reg .pred P;\n\t"
        "LW%=:\n\t"
        "mbarrier.try_wait.parity.shared.b64 P, [%0], %1, 0x989680;\n\t"
        "@P bra LD%=;\n\t"
        "bra LW%=;\n\t"
        "LD%=:\n\t}"
        :: "r"(m), "r"(ph) : "memory");
}
__device__ __forceinline__ void bulk_g2s(uint32_t dst, const void* src, uint32_t bytes, uint32_t mbar) {
    asm volatile("cp.async.bulk.shared::cluster.global.mbarrier::complete_tx::bytes [%0], [%1], %2, [%3];"
                 :: "r"(dst), "l"(src), "r"(bytes), "r"(mbar) : "memory");
}
__device__ __forceinline__ void mma16816(float d[4], const uint32_t a[4], uint32_t b0, uint32_t b1) {
    asm volatile("mma.sync.aligned.m16n8k16.row.col.f32.f16.f16.f32 "
                 "{%0,%1,%2,%3}, {%4,%5,%6,%7}, {%8,%9}, {%0,%1,%2,%3};"
                 : "+f"(d[0]), "+f"(d[1]), "+f"(d[2]), "+f"(d[3])
                 : "r"(a[0]), "r"(a[1]), "r"(a[2]), "r"(a[3]), "r"(b0), "r"(b1));
}
__device__ __forceinline__ void ldsm4(uint32_t r[4], uint32_t addr) {
    asm volatile("ldmatrix.sync.aligned.m8n8.x4.shared.b16 {%0,%1,%2,%3}, [%4];"
                 : "=r"(r[0]), "=r"(r[1]), "=r"(r[2]), "=r"(r[3]) : "r"(addr));
}

// ---------------- prep kernels ----------------
__global__ void __launch_bounds__(256) out_init_kernel(float* __restrict__ out) {
    int idx = blockIdx.x * 256 + threadIdx.x;     // 131072 float4
    float4* o4 = (float4*)out;
    float v = (idx < 65536) ? 0.5f : 0.f;
    o4[idx] = make_float4(v, v, v, v);
}

__global__ void __launch_bounds__(1024) prep_mask_kernel(const float* __restrict__ mm) {
    __shared__ int wcnt[32], woff[33];
    __shared__ int ubase[4], sbase[4], ntl[4];
    int t = threadIdx.x, w = t >> 5, lane = t & 31, b = t >> 8;
    int act = (mm[t] != 0.f);
    unsigned bal = __ballot_sync(0xffffffffu, act);
    if (lane == 0) wcnt[w] = __popc(bal);
    __syncthreads();
    if (t == 0) {
        int s = 0;
        for (int q = 0; q < 32; q++) { woff[q] = s; s += wcnt[q]; }
        woff[32] = s; g_total = s;
        int ub = 0;
        for (int bb = 0; bb < 4; bb++) {
            int jc = woff[bb * 8 + 8] - woff[bb * 8];
            g_jcnt[bb] = jc;
            sbase[bb] = woff[bb * 8];
            int nt = (jc + 63) >> 6;
            ntl[bb] = nt;
            ubase[bb] = ub;
            ub += jc * nt;
        }
        g_U = ub;
    }
    __syncthreads();
    if (act) {
        int pg = woff[w] + __popc(bal & ((1u << lane) - 1u));
        g_jlist[b * Nn + (pg - woff[b * 8])] = t & 255;
        g_gilist[pg] = t;
        g_slot[t] = pg;
        int nt = ntl[b];
        int ub = ubase[b] + (pg - sbase[b]) * nt;
        for (int jt = 0; jt < nt; jt++) g_unit[ub + jt] = (pg << 4) | jt;
    }
}

// W2T: 16 chunks of [k=256 rows x 64B (32 h halves)], row-swizzled by ((k>>1)&3)<<4.
__global__ void __launch_bounds__(256) prep_w2t_kernel(const float* __restrict__ W2) {
    int idx = blockIdx.x * 256 + threadIdx.x;   // 65536
    int hc2 = idx >> 12;
    int rem = idx & 4095;
    int k   = rem >> 4;
    int hp  = (rem & 15) * 2;
    int h   = hc2 * 32 + hp;
    __half2 v = __floats2half2_rn(W2[h * Kk + k], W2[(h + 1) * Kk + k]);
    uint32_t byt = (uint32_t)hc2 * 16384u + (uint32_t)k * 64u
                 + (((uint32_t)hp * 2u) ^ ((((uint32_t)k >> 1) & 3u) << 4));
    *(__half2*)((char*)g_w2t + byt) = v;
}

// TMP[slot][h][c] = sum_a z[gilist[slot]][a] * W1[(a*32+c)*512 + h]
// block = 64 slots x 8 h x 32 c; per-thread 4c x 16slots register tile; vectorized LDS.
#define PT_ZST  0
#define PT_W1S  8704
#define PT_STG  45568
#define PT_SMEM 78336
__global__ void __launch_bounds__(256, 2) prep_tmp_kernel(const float* __restrict__ z,
                                                          const float* __restrict__ W1) {
    extern __shared__ char psm[];
    float* zsT = (float*)(psm + PT_ZST);   // [32 a][68]   (slot fast)
    float* W1s = (float*)(psm + PT_W1S);   // [32 a][288]  (fl = h*36 + c)
    char*  stg = psm + PT_STG;             // [64 sl][512B = 8h x 64B]
    __shared__ int giS[64];

    const int total = g_total;
    const int it = blockIdx.x;
    if (it * 64 >= total) return;
    const int ht = blockIdx.y;
    const int t  = threadIdx.x;

    if (t < 64) giS[t] = (it * 64 + t < total) ? g_gilist[it * 64 + t] : -1;
    __syncthreads();

    for (int idx = t; idx < 64 * 32; idx += 256) {
        int sl = idx >> 5, a = idx & 31;
        zsT[a * 68 + sl] = (giS[sl] >= 0) ? z[giS[sl] * Dd + a] : 0.f;
    }
    for (int idx = t; idx < 32 * 256; idx += 256) {
        int a = idx >> 8, r = idx & 255;
        int c = r >> 3, hloc = r & 7;
        W1s[a * 288 + hloc * 36 + c] = W1[(a * Dd + c) * Hh + ht * 8 + hloc];
    }
    __syncthreads();

    const int sg = t >> 6;          // slot group (16 slots)
    const int ft = t & 63;
    const int h  = ft >> 3;         // 0..7
    const int c4 = (ft & 7) * 4;    // 0,4,..,28

    float acc[4][16];
    #pragma unroll
    for (int i = 0; i < 4; i++)
        #pragma unroll
        for (int ss = 0; ss < 16; ss++) acc[i][ss] = 0.f;

    const float* wp = &W1s[h * 36 + c4];
    const float* zp = &zsT[sg * 16];
    #pragma unroll 4
    for (int a = 0; a < 32; a++) {
        float4 wv = *(const float4*)(wp + a * 288);
        float4 za = *(const float4*)(zp + a * 68);
        float4 zb = *(const float4*)(zp + a * 68 + 4);
        float4 zc = *(const float4*)(zp + a * 68 + 8);
        float4 zd = *(const float4*)(zp + a * 68 + 12);
        float zz[16] = {za.x, za.y, za.z, za.w, zb.x, zb.y, zb.z, zb.w,
                        zc.x, zc.y, zc.z, zc.w, zd.x, zd.y, zd.z, zd.w};
        #pragma unroll
        for (int ss = 0; ss < 16; ss++) {
            acc[0][ss] += wv.x * zz[ss];
            acc[1][ss] += wv.y * zz[ss];
            acc[2][ss] += wv.z * zz[ss];
            acc[3][ss] += wv.w * zz[ss];
        }
    }

    // stage: warp writes are lane-contiguous 256B per slot
    #pragma unroll
    for (int ss = 0; ss < 16; ss++) {
        int sl = sg * 16 + ss;
        char* p = stg + sl * 512 + h * 64 + c4 * 2;
        *(__half2*)(p)     = __floats2half2_rn(acc[0][ss], acc[1][ss]);
        *(__half2*)(p + 4) = __floats2half2_rn(acc[2][ss], acc[3][ss]);
    }
    __syncthreads();

    // copy-out: per-warp contiguous 512B runs
    #pragma unroll
    for (int r = 0; r < 8; r++) {
        int idx = t + 256 * r;
        int sl = idx >> 5, q = idx & 31;
        int s = it * 64 + sl;
        if (s < total) {
            uint4 v = *(const uint4*)(stg + sl * 512 + q * 16);
            *(uint4*)((char*)g_tmph + (size_t)s * 32768 + ht * 512 + q * 16) = v;
        }
    }
}

// ---------------- main kernel (persistent) ----------------
// dyn smem: zjS 4K @0 | tmpS 32K @4096 | W2 2x16K @36864 | h1 2x8K @69632 = 86016
#define ZJ_OFF  0
#define TMP_OFF 4096
#define W2_OFF  36864
#define H1_OFF  69632
#define MAIN_SMEM 86016

__global__ void __launch_bounds__(256, 2)
decoder_hmma_kernel(const float* __restrict__ z, const float* __restrict__ b1,
                    const float* __restrict__ b2, const float* __restrict__ W3,
                    const float* __restrict__ b3, float* __restrict__ out)
{
    extern __shared__ char dsm[];
    __shared__ float b1s[512], b2s[256], w3s[256], part[64];
    __shared__ int jlS[256];
    __shared__ __align__(8) uint64_t mbars[2];

    const int t    = threadIdx.x;
    const int w    = t >> 5;
    const int lane = t & 31;
    const int wr   = w >> 2;
    const int wc   = w & 3;
    const int lr   = lane >> 2;
    const int lc   = (lane & 3) * 2;
    const int mrow = lane & 7;
    const int mg   = lane >> 3;

    const int U  = g_U;
    const int u0 = (int)(((long long)blockIdx.x * U) / GRID_MAIN);
    const int u1 = (int)(((long long)(blockIdx.x + 1) * U) / GRID_MAIN);
    if (u0 >= u1) return;

    const uint32_t smb = s2u(dsm);
    const uint32_t mb0 = s2u(mbars);

    for (int k = t; k < 512; k += 256) b1s[k] = b1[k];
    b2s[t] = b2[t];
    w3s[t] = W3[t];
    if (t == 0) { mbar_init(mb0, 1); mbar_init(mb0 + 8, 1); }
    __syncthreads();
    if (t == 0) {
        mbar_expect(mb0, 16384);
        bulk_g2s(smb + W2_OFF, (const char*)g_w2t, 16384, mb0);
    }

    const float b3v = b3[0];
    const int totalC = (u1 - u0) * 8;
    int C = 0, pw0 = 0, pw1 = 0;
    int bprev = -1, sprev = -1;

    for (int u = u0; u < u1; u++) {
        const int enc = g_unit[u];
        const int s   = enc >> 4;
        const int jt  = enc & 15;
        const int gi  = g_gilist[s];
        const int b   = gi >> 8;

        if (b != bprev) {
            jlS[t] = g_jlist[b * Nn + t];
            bprev = b;
            __syncthreads();
        }
        const int Kact = g_jcnt[b];

        if (s != sprev) {
            const char* gsrc = (const char*)g_tmph + (size_t)s * 32768;
            #pragma unroll
            for (int r8 = 0; r8 < 8; r8++) {
                int idx = t + 256 * r8;
                int row = idx >> 2, q = idx & 3;
                uint4 v = *(const uint4*)(gsrc + row * 64 + q * 16);
                *(uint4*)(dsm + TMP_OFF + row * 64 + ((q * 16) ^ (((row >> 1) & 3) << 4))) = v;
            }
            sprev = s;
        }

        if (t < 64) {
            part[t] = 0.f;
            int idx = jt * 64 + t;
            char* zr = dsm + ZJ_OFF + t * 64;
            uint32_t sw = (((uint32_t)t >> 1) & 3u) << 4;
            if (idx < Kact) {
                const float4* zp = (const float4*)(z + ((size_t)b * Nn + jlS[idx]) * Dd);
                #pragma unroll
                for (int c4 = 0; c4 < 8; c4++) {
                    float4 v = zp[c4];
                    *(__half2*)(zr + (((uint32_t)(c4 * 8))     ^ sw)) = __floats2half2_rn(v.x, v.y);
                    *(__half2*)(zr + (((uint32_t)(c4 * 8 + 4)) ^ sw)) = __floats2half2_rn(v.z, v.w);
                }
            } else {
                #pragma unroll
                for (int c4 = 0; c4 < 8; c4++) {
                    *(__half2*)(zr + (((uint32_t)(c4 * 8))     ^ sw)) = __floats2half2_rn(0.f, 0.f);
                    *(__half2*)(zr + (((uint32_t)(c4 * 8 + 4)) ^ sw)) = __floats2half2_rn(0.f, 0.f);
                }
            }
        }
        __syncthreads();

        float acc2[2][8][4];
        #pragma unroll
        for (int mt = 0; mt < 2; mt++)
            #pragma unroll
            for (int nt = 0; nt < 8; nt++)
                #pragma unroll
                for (int e = 0; e < 4; e++) acc2[mt][nt][e] = 0.f;

        for (int hc = 0; hc < 8; hc++) {
            float acc1[2][2][4];
            #pragma unroll
            for (int mt = 0; mt < 2; mt++)
                #pragma unroll
                for (int nt = 0; nt < 2; nt++)
                    #pragma unroll
                    for (int e = 0; e < 4; e++) acc1[mt][nt][e] = 0.f;

            #pragma unroll
            for (int kk = 0; kk < 2; kk++) {
                const uint32_t cb = (uint32_t)((kk * 16 + (mg >> 1) * 8) * 2);
                uint32_t bf[4];
                {
                    int nh = hc * 64 + wc * 16 + (mg & 1) * 8 + mrow;
                    ldsm4(bf, smb + TMP_OFF + (uint32_t)nh * 64u + (cb ^ ((((uint32_t)nh >> 1) & 3u) << 4)));
                }
                #pragma unroll
                for (int mt = 0; mt < 2; mt++) {
                    uint32_t af[4];
                    int jr = wr * 32 + mt * 16 + (mg & 1) * 8 + mrow;
                    ldsm4(af, smb + ZJ_OFF + (uint32_t)jr * 64u + (cb ^ ((((uint32_t)jr >> 1) & 3u) << 4)));
                    mma16816(acc1[mt][0], af, bf[0], bf[2]);
                    mma16816(acc1[mt][1], af, bf[1], bf[3]);
                }
            }

            char* h1p = dsm + H1_OFF + (C & 1) * 8192;
            const uint32_t h1b = smb + H1_OFF + (uint32_t)(C & 1) * 8192u;
            #pragma unroll
            for (int mt = 0; mt < 2; mt++)
                #pragma unroll
                for (int nt = 0; nt < 2; nt++) {
                    int rl = wr * 32 + mt * 16 + lr;
                    int hl = wc * 16 + nt * 8 + lc;
                    int hg = hc * 64 + hl;
                    uint32_t sw = ((uint32_t)rl & 7u) << 4;
                    float v0 = fmaxf(acc1[mt][nt][0] + b1s[hg],     0.f);
                    float v1 = fmaxf(acc1[mt][nt][1] + b1s[hg + 1], 0.f);
                    float v2 = fmaxf(acc1[mt][nt][2] + b1s[hg],     0.f);
                    float v3 = fmaxf(acc1[mt][nt][3] + b1s[hg + 1], 0.f);
                    *(__half2*)(h1p + rl * 128 + (((uint32_t)(hl * 2)) ^ sw))       = __floats2half2_rn(v0, v1);
                    *(__half2*)(h1p + (rl + 8) * 128 + (((uint32_t)(hl * 2)) ^ sw)) = __floats2half2_rn(v2, v3);
                }

            mbar_wait(mb0, pw0 & 1); pw0++;
            __syncthreads();

            if (t == 0) {
                mbar_expect(mb0 + 8, 16384);
                bulk_g2s(smb + W2_OFF + 16384,
                         (const char*)g_w2t + ((2 * C + 1) & 15) * 16384, 16384, mb0 + 8);
            }

            #pragma unroll
            for (int kk = 0; kk < 2; kk++) {
                const uint32_t kb = (uint32_t)((kk * 16 + (mg >> 1) * 8) * 2);
                uint32_t bfs[4][4];
                #pragma unroll
                for (int p = 0; p < 4; p++) {
                    int n = wc * 64 + p * 16 + (mg & 1) * 8 + mrow;
                    ldsm4(bfs[p], smb + W2_OFF + (uint32_t)n * 64u + (kb ^ ((((uint32_t)n >> 1) & 3u) << 4)));
                }
                #pragma unroll
                for (int mt = 0; mt < 2; mt++) {
                    uint32_t af[4];
                    int rl = wr * 32 + mt * 16 + (mg & 1) * 8 + mrow;
                    ldsm4(af, h1b + (uint32_t)rl * 128u + (kb ^ (((uint32_t)rl & 7u) << 4)));
                    #pragma unroll
                    for (int p = 0; p < 4; p++) {
                        mma16816(acc2[mt][2 * p],     af, bfs[p][0], bfs[p][2]);
                        mma16816(acc2[mt][2 * p + 1], af, bfs[p][1], bfs[p][3]);
                    }
                }
            }

            __syncthreads();
            if (t == 0 && C + 1 < totalC) {
                mbar_expect(mb0, 16384);
                bulk_g2s(smb + W2_OFF,
                         (const char*)g_w2t + ((2 * C + 2) & 15) * 16384, 16384, mb0);
            }
            mbar_wait(mb0 + 8, pw1 & 1); pw1++;

            #pragma unroll
            for (int kk = 0; kk < 2; kk++) {
                const uint32_t kb  = (uint32_t)((kk * 16 + (mg >> 1) * 8) * 2);
                const uint32_t ccb = kb + 64u;
                uint32_t bfs[4][4];
                #pragma unroll
                for (int p = 0; p < 4; p++) {
                    int n = wc * 64 + p * 16 + (mg & 1) * 8 + mrow;
                    ldsm4(bfs[p], smb + W2_OFF + 16384u + (uint32_t)n * 64u + (kb ^ ((((uint32_t)n >> 1) & 3u) << 4)));
                }
                #pragma unroll
                for (int mt = 0; mt < 2; mt++) {
                    uint32_t af[4];
                    int rl = wr * 32 + mt * 16 + (mg & 1) * 8 + mrow;
                    ldsm4(af, h1b + (uint32_t)rl * 128u + (ccb ^ (((uint32_t)rl & 7u) << 4)));
                    #pragma unroll
                    for (int p = 0; p < 4; p++) {
                        mma16816(acc2[mt][2 * p],     af, bfs[p][0], bfs[p][2]);
                        mma16816(acc2[mt][2 * p + 1], af, bfs[p][1], bfs[p][3]);
                    }
                }
            }
            C++;
        }

        float sacc[2][2] = {{0.f, 0.f}, {0.f, 0.f}};
        #pragma unroll
        for (int mt = 0; mt < 2; mt++)
            #pragma unroll
            for (int nt = 0; nt < 8; nt++) {
                int k = wc * 64 + nt * 8 + lc;
                sacc[mt][0] += fmaxf(acc2[mt][nt][0] + b2s[k],     0.f) * w3s[k]
                             + fmaxf(acc2[mt][nt][1] + b2s[k + 1], 0.f) * w3s[k + 1];
                sacc[mt][1] += fmaxf(acc2[mt][nt][2] + b2s[k],     0.f) * w3s[k]
                             + fmaxf(acc2[mt][nt][3] + b2s[k + 1], 0.f) * w3s[k + 1];
            }
        #pragma unroll
        for (int off = 1; off <= 2; off <<= 1) {
            #pragma unroll
            for (int mt = 0; mt < 2; mt++) {
                sacc[mt][0] += __shfl_xor_sync(0xffffffffu, sacc[mt][0], off);
                sacc[mt][1] += __shfl_xor_sync(0xffffffffu, sacc[mt][1], off);
            }
        }
        if ((lane & 3) == 0) {
            #pragma unroll
            for (int mt = 0; mt < 2; mt++) {
                int r0 = wr * 32 + mt * 16 + lr;
                atomicAdd(&part[r0],     sacc[mt][0]);
                atomicAdd(&part[r0 + 8], sacc[mt][1]);
            }
        }
        __syncthreads();
        if (t < 64) {
            int idx = jt * 64 + t;
            if (idx < Kact) {
                int j = jlS[idx];
                float lg = part[t] + b3v;
                size_t o = (size_t)gi * Nn + j;
                out[o] = 1.f / (1.f + __expf(-lg));
                out[(size_t)Bb * Nn * Nn + o] = lg;
            }
        }
        __syncthreads();
    }
}

extern "C" void kernel_launch(void* const* d_in, const int* in_sizes, int n_in,
                              void* d_out, int out_size)
{
    const float* z   = (const float*)d_in[0];
    const float* mmk = (const float*)d_in[1];
    const float* W1  = (const float*)d_in[3];
    const float* b1  = (const float*)d_in[4];
    const float* W2  = (const float*)d_in[5];
    const float* b2  = (const float*)d_in[6];
    const float* W3  = (const float*)d_in[7];
    const float* b3  = (const float*)d_in[8];
    float* out = (float*)d_out;

    cudaFuncSetAttribute(decoder_hmma_kernel,
                         cudaFuncAttributeMaxDynamicSharedMemorySize, MAIN_SMEM);
    cudaFuncSetAttribute(prep_tmp_kernel,
                         cudaFuncAttributeMaxDynamicSharedMemorySize, PT_SMEM);

    out_init_kernel<<<512, 256>>>(out);
    prep_mask_kernel<<<1, 1024>>>(mmk);
    prep_w2t_kernel<<<256, 256>>>(W2);
    prep_tmp_kernel<<<dim3(16, 64), 256, PT_SMEM>>>(z, W1);
    decoder_hmma_kernel<<<GRID_MAIN, 256, MAIN_SMEM>>>(z, b1, b2, W3, b3, out);
}

// round 11
// speedup vs baseline: 1.6199x; 1.0751x over previous
#include <cuda_runtime.h>
#include <cuda_fp16.h>
#include <stdint.h>

#define Bb 4
#define Nn 256
#define Dd 32
#define Hh 512
#define Kk 256
#define GRID_MAIN 296

// device scratch
__device__ uint4 g_tmph[((size_t)Bb*Nn*Hh*Dd*2)/16];   // fp16 TMP per SLOT [s][h 512][c 32]
__device__ uint4 g_w2t [(16*Kk*64)/16];                 // 256 KB fp16 W2^T: 16 chunks [k 256 x 32h]
__device__ uint4 g_w1h [(16384*64)/16];                 // 1 MB fp16 W1 rows [r 16384][32 a], zjS-style swizzle
__device__ int   g_jlist[Bb*Nn];
__device__ int   g_jcnt[Bb];
__device__ int   g_gilist[Bb*Nn];
__device__ int   g_slot[Bb*Nn];
__device__ int   g_total;
__device__ int   g_unit[Bb*Nn*4];                       // (slot<<4)|jt, grouped by slot
__device__ int   g_U;

// ---------------- helpers ----------------
__device__ __forceinline__ uint32_t s2u(const void* p) {
    uint32_t a;
    asm("{ .reg .u64 t; cvta.to.shared.u64 t, %1; cvt.u32.u64 %0, t; }" : "=r"(a) : "l"(p));
    return a;
}
__device__ __forceinline__ void mbar_init(uint32_t m, uint32_t c) {
    asm volatile("mbarrier.init.shared.b64 [%0], %1;" :: "r"(m), "r"(c) : "memory");
}
__device__ __forceinline__ void mbar_expect(uint32_t m, uint32_t bytes) {
    asm volatile("mbarrier.arrive.expect_tx.shared.b64 _, [%0], %1;" :: "r"(m), "r"(bytes) : "memory");
}
__device__ __forceinline__ void mbar_wait(uint32_t m, uint32_t ph) {
    asm volatile(
        "{\n\t.reg .pred P;\n\t"
        "LW%=:\n\t"
        "mbarrier.try_wait.parity.shared.b64 P, [%0], %1, 0x989680;\n\t"
        "@P bra LD%=;\n\t"
        "bra LW%=;\n\t"
        "LD%=:\n\t}"
        :: "r"(m), "r"(ph) : "memory");
}
__device__ __forceinline__ void bulk_g2s(uint32_t dst, const void* src, uint32_t bytes, uint32_t mbar) {
    asm volatile("cp.async.bulk.shared::cluster.global.mbarrier::complete_tx::bytes [%0], [%1], %2, [%3];"
                 :: "r"(dst), "l"(src), "r"(bytes), "r"(mbar) : "memory");
}
__device__ __forceinline__ void mma16816(float d[4], const uint32_t a[4], uint32_t b0, uint32_t b1) {
    asm volatile("mma.sync.aligned.m16n8k16.row.col.f32.f16.f16.f32 "
                 "{%0,%1,%2,%3}, {%4,%5,%6,%7}, {%8,%9}, {%0,%1,%2,%3};"
                 : "+f"(d[0]), "+f"(d[1]), "+f"(d[2]), "+f"(d[3])
                 : "r"(a[0]), "r"(a[1]), "r"(a[2]), "r"(a[3]), "r"(b0), "r"(b1));
}
__device__ __forceinline__ void ldsm4(uint32_t r[4], uint32_t addr) {
    asm volatile("ldmatrix.sync.aligned.m8n8.x4.shared.b16 {%0,%1,%2,%3}, [%4];"
                 : "=r"(r[0]), "=r"(r[1]), "=r"(r[2]), "=r"(r[3]) : "r"(addr));
}

// ---------------- prep kernels ----------------
__global__ void __launch_bounds__(256) out_init_kernel(float* __restrict__ out) {
    int idx = blockIdx.x * 256 + threadIdx.x;     // 131072 float4
    float4* o4 = (float4*)out;
    float v = (idx < 65536) ? 0.5f : 0.f;
    o4[idx] = make_float4(v, v, v, v);
}

__global__ void __launch_bounds__(1024) prep_mask_kernel(const float* __restrict__ mm) {
    __shared__ int wcnt[32], woff[33];
    __shared__ int ubase[4], sbase[4], ntl[4];
    int t = threadIdx.x, w = t >> 5, lane = t & 31, b = t >> 8;
    int act = (mm[t] != 0.f);
    unsigned bal = __ballot_sync(0xffffffffu, act);
    if (lane == 0) wcnt[w] = __popc(bal);
    __syncthreads();
    if (t == 0) {
        int s = 0;
        for (int q = 0; q < 32; q++) { woff[q] = s; s += wcnt[q]; }
        woff[32] = s; g_total = s;
        int ub = 0;
        for (int bb = 0; bb < 4; bb++) {
            int jc = woff[bb * 8 + 8] - woff[bb * 8];
            g_jcnt[bb] = jc;
            sbase[bb] = woff[bb * 8];
            int nt = (jc + 63) >> 6;
            ntl[bb] = nt;
            ubase[bb] = ub;
            ub += jc * nt;
        }
        g_U = ub;
    }
    __syncthreads();
    if (act) {
        int pg = woff[w] + __popc(bal & ((1u << lane) - 1u));
        g_jlist[b * Nn + (pg - woff[b * 8])] = t & 255;
        g_gilist[pg] = t;
        g_slot[t] = pg;
        int nt = ntl[b];
        int ub = ubase[b] + (pg - sbase[b]) * nt;
        for (int jt = 0; jt < nt; jt++) g_unit[ub + jt] = (pg << 4) | jt;
    }
}

// W2T: 16 chunks of [k=256 rows x 64B (32 h halves)], row-swizzled by ((k>>1)&3)<<4.
__global__ void __launch_bounds__(256) prep_w2t_kernel(const float* __restrict__ W2) {
    int idx = blockIdx.x * 256 + threadIdx.x;   // 65536
    int hc2 = idx >> 12;
    int rem = idx & 4095;
    int k   = rem >> 4;
    int hp  = (rem & 15) * 2;
    int h   = hc2 * 32 + hp;
    __half2 v = __floats2half2_rn(W2[h * Kk + k], W2[(h + 1) * Kk + k]);
    uint32_t byt = (uint32_t)hc2 * 16384u + (uint32_t)k * 64u
                 + (((uint32_t)hp * 2u) ^ ((((uint32_t)k >> 1) & 3u) << 4));
    *(__half2*)((char*)g_w2t + byt) = v;
}

// W1h: rows r = (h>>1)*64 + (h&1)*32 + c, 64B of 32 a-halves, swizzle ((r>>1)&3)<<4.
// Block ht handles h in [ht*16, ht*16+16). Staging tile2[h_loc][c*33 + a] for conflict-free access.
#define WH_SMEM (16 * 1057 * 4)
__global__ void __launch_bounds__(256) prep_w1h_kernel(const float* __restrict__ W1) {
    extern __shared__ float tile2[];   // [16][1057]
    const int ht = blockIdx.x, t = threadIdx.x;
    #pragma unroll
    for (int l = 0; l < 64; l++) {
        int idx = t + 256 * l;
        int row = idx >> 4, hl = idx & 15;      // row = a*32+c
        int a = row >> 5, c = row & 31;
        tile2[hl * 1057 + c * 33 + a] = W1[row * Hh + ht * 16 + hl];
    }
    __syncthreads();
    #pragma unroll
    for (int l = 0; l < 32; l++) {
        int idx = t + 256 * l;
        int a2 = idx & 15, rl = idx >> 4;       // rl in [0,512)
        int hl = ((rl >> 6) << 1) + ((rl >> 5) & 1);
        int c  = rl & 31;
        float v0 = tile2[hl * 1057 + c * 33 + 2 * a2];
        float v1 = tile2[hl * 1057 + c * 33 + 2 * a2 + 1];
        uint32_t byt = (uint32_t)(ht * 512 + rl) * 64u
                     + (((uint32_t)a2 * 4u) ^ ((((uint32_t)rl >> 1) & 3u) << 4));
        *(__half2*)((char*)g_w1h + byt) = __floats2half2_rn(v0, v1);
    }
}

// TMP via HMMA: per block 64 slots x 1024 f (16 chunks of 64 rows). Identical fragment
// machinery to main's MMA1. TMP[s] byte offset of row r is exactly r*2 (= h*64 + c*2).
#define PM_ZA   0
#define PM_B    4096
#define PM_STG  12288
#define PM_SMEM 20480
__global__ void __launch_bounds__(256) prep_tmpmma_kernel(const float* __restrict__ z) {
    extern __shared__ char psm[];
    __shared__ __align__(8) uint64_t pmb[2];
    __shared__ int giS2[64];

    const int total = g_total;
    const int it = blockIdx.x;
    if (it * 64 >= total) return;
    const int fc = blockIdx.y;
    const int t  = threadIdx.x;
    const int w    = t >> 5;
    const int lane = t & 31;
    const int wr   = w >> 2;
    const int wc   = w & 3;
    const int lr   = lane >> 2;
    const int lc   = (lane & 3) * 2;
    const int mrow = lane & 7;
    const int mg   = lane >> 3;

    const uint32_t smb = s2u(psm);
    const uint32_t mb  = s2u(pmb);

    if (t < 64) giS2[t] = (it * 64 + t < total) ? g_gilist[it * 64 + t] : -1;
    if (t == 0) { mbar_init(mb, 1); mbar_init(mb + 8, 1); }
    __syncthreads();

    if (t < 64) {   // A tile: 64 slots x 64B, zjS format
        char* zr = psm + PM_ZA + t * 64;
        uint32_t sw = (((uint32_t)t >> 1) & 3u) << 4;
        int gi = giS2[t];
        if (gi >= 0) {
            const float4* zp = (const float4*)(z + (size_t)gi * Dd);
            #pragma unroll
            for (int c4 = 0; c4 < 8; c4++) {
                float4 v = zp[c4];
                *(__half2*)(zr + (((uint32_t)(c4 * 8))     ^ sw)) = __floats2half2_rn(v.x, v.y);
                *(__half2*)(zr + (((uint32_t)(c4 * 8 + 4)) ^ sw)) = __floats2half2_rn(v.z, v.w);
            }
        } else {
            #pragma unroll
            for (int c4 = 0; c4 < 8; c4++) {
                *(__half2*)(zr + (((uint32_t)(c4 * 8))     ^ sw)) = __floats2half2_rn(0.f, 0.f);
                *(__half2*)(zr + (((uint32_t)(c4 * 8 + 4)) ^ sw)) = __floats2half2_rn(0.f, 0.f);
            }
        }
    }
    if (t == 0) {
        mbar_expect(mb, 4096);
        bulk_g2s(smb + PM_B,        (const char*)g_w1h + (size_t)(fc * 16 + 0) * 4096, 4096, mb);
        mbar_expect(mb + 8, 4096);
        bulk_g2s(smb + PM_B + 4096, (const char*)g_w1h + (size_t)(fc * 16 + 1) * 4096, 4096, mb + 8);
    }
    __syncthreads();   // A visible

    int pw[2] = {0, 0};
    for (int q = 0; q < 16; q++) {
        const int buf = q & 1;
        mbar_wait(mb + buf * 8, pw[buf] & 1); pw[buf]++;
        __syncthreads();   // B visible; prev chunk's stg copy-reads done

        float acc1[2][2][4];
        #pragma unroll
        for (int mt = 0; mt < 2; mt++)
            #pragma unroll
            for (int nt = 0; nt < 2; nt++)
                #pragma unroll
                for (int e = 0; e < 4; e++) acc1[mt][nt][e] = 0.f;

        const uint32_t bbase = smb + PM_B + (uint32_t)buf * 4096u;
        #pragma unroll
        for (int kk = 0; kk < 2; kk++) {
            const uint32_t cb = (uint32_t)((kk * 16 + (mg >> 1) * 8) * 2);
            uint32_t bf[4];
            {
                int nh = wc * 16 + (mg & 1) * 8 + mrow;
                ldsm4(bf, bbase + (uint32_t)nh * 64u + (cb ^ ((((uint32_t)nh >> 1) & 3u) << 4)));
            }
            #pragma unroll
            for (int mt = 0; mt < 2; mt++) {
                uint32_t af[4];
                int jr = wr * 32 + mt * 16 + (mg & 1) * 8 + mrow;
                ldsm4(af, smb + PM_ZA + (uint32_t)jr * 64u + (cb ^ ((((uint32_t)jr >> 1) & 3u) << 4)));
                mma16816(acc1[mt][0], af, bf[0], bf[2]);
                mma16816(acc1[mt][1], af, bf[1], bf[3]);
            }
        }

        // fragments -> stg (64 slots x 128B rows, swizzle (rl&7)<<4)
        #pragma unroll
        for (int mt = 0; mt < 2; mt++)
            #pragma unroll
            for (int nt = 0; nt < 2; nt++) {
                int rl = wr * 32 + mt * 16 + lr;
                int hl = wc * 16 + nt * 8 + lc;
                uint32_t sw = ((uint32_t)rl & 7u) << 4;
                *(__half2*)(psm + PM_STG + rl * 128 + (((uint32_t)(hl * 2)) ^ sw))
                    = __floats2half2_rn(acc1[mt][nt][0], acc1[mt][nt][1]);
                *(__half2*)(psm + PM_STG + (rl + 8) * 128 + (((uint32_t)(hl * 2)) ^ sw))
                    = __floats2half2_rn(acc1[mt][nt][2], acc1[mt][nt][3]);
            }
        __syncthreads();   // stg complete; B buf reads complete

        if (t == 0 && q + 2 < 16) {
            mbar_expect(mb + buf * 8, 4096);
            bulk_g2s(smb + PM_B + (uint32_t)buf * 4096u,
                     (const char*)g_w1h + (size_t)(fc * 16 + q + 2) * 4096, 4096, mb + buf * 8);
        }

        const int qg = fc * 16 + q;
        #pragma unroll
        for (int l = 0; l < 2; l++) {
            int idx = t + 256 * l;
            int sl = idx >> 3, qt = idx & 7;
            int s = it * 64 + sl;
            if (s < total) {
                uint4 v = *(const uint4*)(psm + PM_STG + sl * 128 + ((qt * 16) ^ ((sl & 7) << 4)));
                *(uint4*)((char*)g_tmph + (size_t)s * 32768 + qg * 128 + qt * 16) = v;
            }
        }
    }
}

// ---------------- main kernel (persistent) ----------------
// dyn smem: zjS 4K @0 | tmpS 32K @4096 | W2 2x16K @36864 | h1 2x8K @69632 = 86016
#define ZJ_OFF  0
#define TMP_OFF 4096
#define W2_OFF  36864
#define H1_OFF  69632
#define MAIN_SMEM 86016

__global__ void __launch_bounds__(256, 2)
decoder_hmma_kernel(const float* __restrict__ z, const float* __restrict__ b1,
                    const float* __restrict__ b2, const float* __restrict__ W3,
                    const float* __restrict__ b3, float* __restrict__ out)
{
    extern __shared__ char dsm[];
    __shared__ float b1s[512], b2s[256], w3s[256], part[64];
    __shared__ int jlS[256];
    __shared__ __align__(8) uint64_t mbars[2];

    const int t    = threadIdx.x;
    const int w    = t >> 5;
    const int lane = t & 31;
    const int wr   = w >> 2;
    const int wc   = w & 3;
    const int lr   = lane >> 2;
    const int lc   = (lane & 3) * 2;
    const int mrow = lane & 7;
    const int mg   = lane >> 3;

    const int U  = g_U;
    const int u0 = (int)(((long long)blockIdx.x * U) / GRID_MAIN);
    const int u1 = (int)(((long long)(blockIdx.x + 1) * U) / GRID_MAIN);
    if (u0 >= u1) return;

    const uint32_t smb = s2u(dsm);
    const uint32_t mb0 = s2u(mbars);

    for (int k = t; k < 512; k += 256) b1s[k] = b1[k];
    b2s[t] = b2[t];
    w3s[t] = W3[t];
    if (t == 0) { mbar_init(mb0, 1); mbar_init(mb0 + 8, 1); }
    __syncthreads();
    if (t == 0) {
        mbar_expect(mb0, 16384);
        bulk_g2s(smb + W2_OFF, (const char*)g_w2t, 16384, mb0);
    }

    const float b3v = b3[0];
    const int totalC = (u1 - u0) * 8;
    int C = 0, pw0 = 0, pw1 = 0;
    int bprev = -1, sprev = -1;

    for (int u = u0; u < u1; u++) {
        const int enc = g_unit[u];
        const int s   = enc >> 4;
        const int jt  = enc & 15;
        const int gi  = g_gilist[s];
        const int b   = gi >> 8;

        if (b != bprev) {
            jlS[t] = g_jlist[b * Nn + t];
            bprev = b;
            __syncthreads();
        }
        const int Kact = g_jcnt[b];

        if (s != sprev) {
            const char* gsrc = (const char*)g_tmph + (size_t)s * 32768;
            #pragma unroll
            for (int r8 = 0; r8 < 8; r8++) {
                int idx = t + 256 * r8;
                int row = idx >> 2, q = idx & 3;
                uint4 v = *(const uint4*)(gsrc + row * 64 + q * 16);
                *(uint4*)(dsm + TMP_OFF + row * 64 + ((q * 16) ^ (((row >> 1) & 3) << 4))) = v;
            }
            sprev = s;
        }

        if (t < 64) {
            part[t] = 0.f;
            int idx = jt * 64 + t;
            char* zr = dsm + ZJ_OFF + t * 64;
            uint32_t sw = (((uint32_t)t >> 1) & 3u) << 4;
            if (idx < Kact) {
                const float4* zp = (const float4*)(z + ((size_t)b * Nn + jlS[idx]) * Dd);
                #pragma unroll
                for (int c4 = 0; c4 < 8; c4++) {
                    float4 v = zp[c4];
                    *(__half2*)(zr + (((uint32_t)(c4 * 8))     ^ sw)) = __floats2half2_rn(v.x, v.y);
                    *(__half2*)(zr + (((uint32_t)(c4 * 8 + 4)) ^ sw)) = __floats2half2_rn(v.z, v.w);
                }
            } else {
                #pragma unroll
                for (int c4 = 0; c4 < 8; c4++) {
                    *(__half2*)(zr + (((uint32_t)(c4 * 8))     ^ sw)) = __floats2half2_rn(0.f, 0.f);
                    *(__half2*)(zr + (((uint32_t)(c4 * 8 + 4)) ^ sw)) = __floats2half2_rn(0.f, 0.f);
                }
            }
        }
        __syncthreads();

        float acc2[2][8][4];
        #pragma unroll
        for (int mt = 0; mt < 2; mt++)
            #pragma unroll
            for (int nt = 0; nt < 8; nt++)
                #pragma unroll
                for (int e = 0; e < 4; e++) acc2[mt][nt][e] = 0.f;

        for (int hc = 0; hc < 8; hc++) {
            float acc1[2][2][4];
            #pragma unroll
            for (int mt = 0; mt < 2; mt++)
                #pragma unroll
                for (int nt = 0; nt < 2; nt++)
                    #pragma unroll
                    for (int e = 0; e < 4; e++) acc1[mt][nt][e] = 0.f;

            #pragma unroll
            for (int kk = 0; kk < 2; kk++) {
                const uint32_t cb = (uint32_t)((kk * 16 + (mg >> 1) * 8) * 2);
                uint32_t bf[4];
                {
                    int nh = hc * 64 + wc * 16 + (mg & 1) * 8 + mrow;
                    ldsm4(bf, smb + TMP_OFF + (uint32_t)nh * 64u + (cb ^ ((((uint32_t)nh >> 1) & 3u) << 4)));
                }
                #pragma unroll
                for (int mt = 0; mt < 2; mt++) {
                    uint32_t af[4];
                    int jr = wr * 32 + mt * 16 + (mg & 1) * 8 + mrow;
                    ldsm4(af, smb + ZJ_OFF + (uint32_t)jr * 64u + (cb ^ ((((uint32_t)jr >> 1) & 3u) << 4)));
                    mma16816(acc1[mt][0], af, bf[0], bf[2]);
                    mma16816(acc1[mt][1], af, bf[1], bf[3]);
                }
            }

            char* h1p = dsm + H1_OFF + (C & 1) * 8192;
            const uint32_t h1b = smb + H1_OFF + (uint32_t)(C & 1) * 8192u;
            #pragma unroll
            for (int mt = 0; mt < 2; mt++)
                #pragma unroll
                for (int nt = 0; nt < 2; nt++) {
                    int rl = wr * 32 + mt * 16 + lr;
                    int hl = wc * 16 + nt * 8 + lc;
                    int hg = hc * 64 + hl;
                    uint32_t sw = ((uint32_t)rl & 7u) << 4;
                    float v0 = fmaxf(acc1[mt][nt][0] + b1s[hg],     0.f);
                    float v1 = fmaxf(acc1[mt][nt][1] + b1s[hg + 1], 0.f);
                    float v2 = fmaxf(acc1[mt][nt][2] + b1s[hg],     0.f);
                    float v3 = fmaxf(acc1[mt][nt][3] + b1s[hg + 1], 0.f);
                    *(__half2*)(h1p + rl * 128 + (((uint32_t)(hl * 2)) ^ sw))       = __floats2half2_rn(v0, v1);
                    *(__half2*)(h1p + (rl + 8) * 128 + (((uint32_t)(hl * 2)) ^ sw)) = __floats2half2_rn(v2, v3);
                }

            mbar_wait(mb0, pw0 & 1); pw0++;
            __syncthreads();

            if (t == 0) {
                mbar_expect(mb0 + 8, 16384);
                bulk_g2s(smb + W2_OFF + 16384,
                         (const char*)g_w2t + ((2 * C + 1) & 15) * 16384, 16384, mb0 + 8);
            }

            #pragma unroll
            for (int kk = 0; kk < 2; kk++) {
                const uint32_t kb = (uint32_t)((kk * 16 + (mg >> 1) * 8) * 2);
                uint32_t bfs[4][4];
                #pragma unroll
                for (int p = 0; p < 4; p++) {
                    int n = wc * 64 + p * 16 + (mg & 1) * 8 + mrow;
                    ldsm4(bfs[p], smb + W2_OFF + (uint32_t)n * 64u + (kb ^ ((((uint32_t)n >> 1) & 3u) << 4)));
                }
                #pragma unroll
                for (int mt = 0; mt < 2; mt++) {
                    uint32_t af[4];
                    int rl = wr * 32 + mt * 16 + (mg & 1) * 8 + mrow;
                    ldsm4(af, h1b + (uint32_t)rl * 128u + (kb ^ (((uint32_t)rl & 7u) << 4)));
                    #pragma unroll
                    for (int p = 0; p < 4; p++) {
                        mma16816(acc2[mt][2 * p],     af, bfs[p][0], bfs[p][2]);
                        mma16816(acc2[mt][2 * p + 1], af, bfs[p][1], bfs[p][3]);
                    }
                }
            }

            __syncthreads();
            if (t == 0 && C + 1 < totalC) {
                mbar_expect(mb0, 16384);
                bulk_g2s(smb + W2_OFF,
                         (const char*)g_w2t + ((2 * C + 2) & 15) * 16384, 16384, mb0);
            }
            mbar_wait(mb0 + 8, pw1 & 1); pw1++;

            #pragma unroll
            for (int kk = 0; kk < 2; kk++) {
                const uint32_t kb  = (uint32_t)((kk * 16 + (mg >> 1) * 8) * 2);
                const uint32_t ccb = kb + 64u;
                uint32_t bfs[4][4];
                #pragma unroll
                for (int p = 0; p < 4; p++) {
                    int n = wc * 64 + p * 16 + (mg & 1) * 8 + mrow;
                    ldsm4(bfs[p], smb + W2_OFF + 16384u + (uint32_t)n * 64u + (kb ^ ((((uint32_t)n >> 1) & 3u) << 4)));
                }
                #pragma unroll
                for (int mt = 0; mt < 2; mt++) {
                    uint32_t af[4];
                    int rl = wr * 32 + mt * 16 + (mg & 1) * 8 + mrow;
                    ldsm4(af, h1b + (uint32_t)rl * 128u + (ccb ^ (((uint32_t)rl & 7u) << 4)));
                    #pragma unroll
                    for (int p = 0; p < 4; p++) {
                        mma16816(acc2[mt][2 * p],     af, bfs[p][0], bfs[p][2]);
                        mma16816(acc2[mt][2 * p + 1], af, bfs[p][1], bfs[p][3]);
                    }
                }
            }
            C++;
        }

        float sacc[2][2] = {{0.f, 0.f}, {0.f, 0.f}};
        #pragma unroll
        for (int mt = 0; mt < 2; mt++)
            #pragma unroll
            for (int nt = 0; nt < 8; nt++) {
                int k = wc * 64 + nt * 8 + lc;
                sacc[mt][0] += fmaxf(acc2[mt][nt][0] + b2s[k],     0.f) * w3s[k]
                             + fmaxf(acc2[mt][nt][1] + b2s[k + 1], 0.f) * w3s[k + 1];
                sacc[mt][1] += fmaxf(acc2[mt][nt][2] + b2s[k],     0.f) * w3s[k]
                             + fmaxf(acc2[mt][nt][3] + b2s[k + 1], 0.f) * w3s[k + 1];
            }
        #pragma unroll
        for (int off = 1; off <= 2; off <<= 1) {
            #pragma unroll
            for (int mt = 0; mt < 2; mt++) {
                sacc[mt][0] += __shfl_xor_sync(0xffffffffu, sacc[mt][0], off);
                sacc[mt][1] += __shfl_xor_sync(0xffffffffu, sacc[mt][1], off);
            }
        }
        if ((lane & 3) == 0) {
            #pragma unroll
            for (int mt = 0; mt < 2; mt++) {
                int r0 = wr * 32 + mt * 16 + lr;
                atomicAdd(&part[r0],     sacc[mt][0]);
                atomicAdd(&part[r0 + 8], sacc[mt][1]);
            }
        }
        __syncthreads();
        if (t < 64) {
            int idx = jt * 64 + t;
            if (idx < Kact) {
                int j = jlS[idx];
                float lg = part[t] + b3v;
                size_t o = (size_t)gi * Nn + j;
                out[o] = 1.f / (1.f + __expf(-lg));
                out[(size_t)Bb * Nn * Nn + o] = lg;
            }
        }
        __syncthreads();
    }
}

extern "C" void kernel_launch(void* const* d_in, const int* in_sizes, int n_in,
                              void* d_out, int out_size)
{
    const float* z   = (const float*)d_in[0];
    const float* mmk = (const float*)d_in[1];
    const float* W1  = (const float*)d_in[3];
    const float* b1  = (const float*)d_in[4];
    const float* W2  = (const float*)d_in[5];
    const float* b2  = (const float*)d_in[6];
    const float* W3  = (const float*)d_in[7];
    const float* b3  = (const float*)d_in[8];
    float* out = (float*)d_out;

    cudaFuncSetAttribute(decoder_hmma_kernel,
                         cudaFuncAttributeMaxDynamicSharedMemorySize, MAIN_SMEM);
    cudaFuncSetAttribute(prep_w1h_kernel,
                         cudaFuncAttributeMaxDynamicSharedMemorySize, WH_SMEM);

    out_init_kernel<<<512, 256>>>(out);
    prep_mask_kernel<<<1, 1024>>>(mmk);
    prep_w2t_kernel<<<256, 256>>>(W2);
    prep_w1h_kernel<<<32, 256, WH_SMEM>>>(W1);
    prep_tmpmma_kernel<<<dim3(8, 16), 256, PM_SMEM>>>(z);
    decoder_hmma_kernel<<<GRID_MAIN, 256, MAIN_SMEM>>>(z, b1, b2, W3, b3, out);
}

// round 13
// speedup vs baseline: 1.7118x; 1.0568x over previous
#include <cuda_runtime.h>
#include <cuda_fp16.h>
#include <stdint.h>

#define Bb 4
#define Nn 256
#define Dd 32
#define Hh 512
#define Kk 256
#define GRID_MAIN 296

// device scratch
__device__ uint4 g_tmph[((size_t)Bb*Nn*Hh*Dd*2)/16];   // fp16 TMP per SLOT [s][h 512][c 32]
__device__ uint4 g_w2t [(16*Kk*64)/16];                 // 256 KB fp16 W2^T: 16 chunks [k 256 x 32h]
__device__ uint4 g_w1h [(16384*64)/16];                 // 1 MB fp16 W1 rows [r 16384][32 a], zjS-style swizzle
__device__ int   g_jlist[Bb*Nn];
__device__ int   g_jcnt[Bb];
__device__ int   g_gilist[Bb*Nn];
__device__ int   g_slot[Bb*Nn];
__device__ int   g_total;
__device__ int   g_unit[Bb*Nn*4];                       // (slot<<4)|jt, grouped by slot
__device__ int   g_U;

// ---------------- helpers ----------------
__device__ __forceinline__ uint32_t s2u(const void* p) {
    uint32_t a;
    asm("{ .reg .u64 t; cvta.to.shared.u64 t, %1; cvt.u32.u64 %0, t; }" : "=r"(a) : "l"(p));
    return a;
}
__device__ __forceinline__ void mbar_init(uint32_t m, uint32_t c) {
    asm volatile("mbarrier.init.shared.b64 [%0], %1;" :: "r"(m), "r"(c) : "memory");
}
__device__ __forceinline__ void mbar_expect(uint32_t m, uint32_t bytes) {
    asm volatile("mbarrier.arrive.expect_tx.shared.b64 _, [%0], %1;" :: "r"(m), "r"(bytes) : "memory");
}
__device__ __forceinline__ void mbar_wait(uint32_t m, uint32_t ph) {
    asm volatile(
        "{\n\t.reg .pred P;\n\t"
        "LW%=:\n\t"
        "mbarrier.try_wait.parity.shared.b64 P, [%0], %1, 0x989680;\n\t"
        "@P bra LD%=;\n\t"
        "bra LW%=;\n\t"
        "LD%=:\n\t}"
        :: "r"(m), "r"(ph) : "memory");
}
__device__ __forceinline__ void bulk_g2s(uint32_t dst, const void* src, uint32_t bytes, uint32_t mbar) {
    asm volatile("cp.async.bulk.shared::cluster.global.mbarrier::complete_tx::bytes [%0], [%1], %2, [%3];"
                 :: "r"(dst), "l"(src), "r"(bytes), "r"(mbar) : "memory");
}
__device__ __forceinline__ void mma16816(float d[4], const uint32_t a[4], uint32_t b0, uint32_t b1) {
    asm volatile("mma.sync.aligned.m16n8k16.row.col.f32.f16.f16.f32 "
                 "{%0,%1,%2,%3}, {%4,%5,%6,%7}, {%8,%9}, {%0,%1,%2,%3};"
                 : "+f"(d[0]), "+f"(d[1]), "+f"(d[2]), "+f"(d[3])
                 : "r"(a[0]), "r"(a[1]), "r"(a[2]), "r"(a[3]), "r"(b0), "r"(b1));
}
__device__ __forceinline__ void ldsm4(uint32_t r[4], uint32_t addr) {
    asm volatile("ldmatrix.sync.aligned.m8n8.x4.shared.b16 {%0,%1,%2,%3}, [%4];"
                 : "=r"(r[0]), "=r"(r[1]), "=r"(r[2]), "=r"(r[3]) : "r"(addr));
}

// ---------------- fused prep (out_init + w2t + w1h) ----------------
// blocks [0,512): out_init | [512,768): w2t | [768,896): w1h (ht = q>>2, aq = q&3)
__global__ void __launch_bounds__(256) prep_all_kernel(float* __restrict__ out,
                                                       const float* __restrict__ W2,
                                                       const float* __restrict__ W1) {
    __shared__ float tile2[16 * 289];   // 18.5 KB (w1h role only)
    const int blk = blockIdx.x;
    const int t   = threadIdx.x;

    if (blk < 512) {                    // ---- out_init ----
        int idx = blk * 256 + t;        // 131072 float4
        float4* o4 = (float4*)out;
        float v = (idx < 65536) ? 0.5f : 0.f;
        o4[idx] = make_float4(v, v, v, v);
        return;
    }
    if (blk < 768) {                    // ---- w2t: 16 chunks [k 256 x 32h], swizzle ((k>>1)&3)<<4
        int idx = (blk - 512) * 256 + t;    // 65536
        int hc2 = idx >> 12;
        int rem = idx & 4095;
        int k   = rem >> 4;
        int hp  = (rem & 15) * 2;
        int h   = hc2 * 32 + hp;
        __half2 v = __floats2half2_rn(W2[h * Kk + k], W2[(h + 1) * Kk + k]);
        uint32_t byt = (uint32_t)hc2 * 16384u + (uint32_t)k * 64u
                     + (((uint32_t)hp * 2u) ^ ((((uint32_t)k >> 1) & 3u) << 4));
        *(__half2*)((char*)g_w2t + byt) = v;
        return;
    }
    // ---- w1h: rows r = (h>>1)*64 + (h&1)*32 + c, 64B of 32 a-halves, swizzle ((r>>1)&3)<<4.
    // block (ht, aq): h in [ht*16, ht*16+16), a in [aq*8, aq*8+8).
    const int q  = blk - 768;
    const int ht = q >> 2;
    const int aq = q & 3;
    #pragma unroll
    for (int l = 0; l < 16; l++) {
        int idx = t + 256 * l;              // 4096 = 256 rowl x 16 hl
        int hl = idx & 15, rowl = idx >> 4;
        int a_l = rowl >> 5, c = rowl & 31;
        int grow = (aq * 8 + a_l) * 32 + c;
        tile2[hl * 289 + c * 9 + a_l] = W1[grow * Hh + ht * 16 + hl];
    }
    __syncthreads();
    #pragma unroll
    for (int l = 0; l < 8; l++) {
        int idx = t + 256 * l;              // 2048 = 512 rl x 4 a2l
        int a2l = idx & 3, rl = idx >> 2;
        int hl = ((rl >> 6) << 1) + ((rl >> 5) & 1);
        int c  = rl & 31;
        int a2 = aq * 4 + a2l;
        float v0 = tile2[hl * 289 + c * 9 + 2 * a2l];
        float v1 = tile2[hl * 289 + c * 9 + 2 * a2l + 1];
        uint32_t byt = (uint32_t)(ht * 512 + rl) * 64u
                     + (((uint32_t)a2 * 4u) ^ ((((uint32_t)rl >> 1) & 3u) << 4));
        *(__half2*)((char*)g_w1h + byt) = __floats2half2_rn(v0, v1);
    }
}

__global__ void __launch_bounds__(1024) prep_mask_kernel(const float* __restrict__ mm) {
    __shared__ int wcnt[32], woff[33];
    __shared__ int ubase[4], sbase[4], ntl[4];
    int t = threadIdx.x, w = t >> 5, lane = t & 31, b = t >> 8;
    int act = (mm[t] != 0.f);
    unsigned bal = __ballot_sync(0xffffffffu, act);
    if (lane == 0) wcnt[w] = __popc(bal);
    __syncthreads();
    if (t == 0) {
        int s = 0;
        for (int q = 0; q < 32; q++) { woff[q] = s; s += wcnt[q]; }
        woff[32] = s; g_total = s;
        int ub = 0;
        for (int bb = 0; bb < 4; bb++) {
            int jc = woff[bb * 8 + 8] - woff[bb * 8];
            g_jcnt[bb] = jc;
            sbase[bb] = woff[bb * 8];
            int nt = (jc + 63) >> 6;
            ntl[bb] = nt;
            ubase[bb] = ub;
            ub += jc * nt;
        }
        g_U = ub;
    }
    __syncthreads();
    if (act) {
        int pg = woff[w] + __popc(bal & ((1u << lane) - 1u));
        g_jlist[b * Nn + (pg - woff[b * 8])] = t & 255;
        g_gilist[pg] = t;
        g_slot[t] = pg;
        int nt = ntl[b];
        int ub = ubase[b] + (pg - sbase[b]) * nt;
        for (int jt = 0; jt < nt; jt++) g_unit[ub + jt] = (pg << 4) | jt;
    }
}

// TMP via HMMA: per block 64 slots x 1024 f (16 chunks of 64 rows).
#define PM_ZA   0
#define PM_B    4096
#define PM_STG  12288
#define PM_SMEM 20480
__global__ void __launch_bounds__(256) prep_tmpmma_kernel(const float* __restrict__ z) {
    extern __shared__ char psm[];
    __shared__ __align__(8) uint64_t pmb[2];
    __shared__ int giS2[64];

    const int total = g_total;
    const int it = blockIdx.x;
    if (it * 64 >= total) return;
    const int fc = blockIdx.y;
    const int t  = threadIdx.x;
    const int w    = t >> 5;
    const int lane = t & 31;
    const int wr   = w >> 2;
    const int wc   = w & 3;
    const int lr   = lane >> 2;
    const int lc   = (lane & 3) * 2;
    const int mrow = lane & 7;
    const int mg   = lane >> 3;

    const uint32_t smb = s2u(psm);
    const uint32_t mb  = s2u(pmb);

    if (t < 64) giS2[t] = (it * 64 + t < total) ? g_gilist[it * 64 + t] : -1;
    if (t == 0) { mbar_init(mb, 1); mbar_init(mb + 8, 1); }
    __syncthreads();

    if (t < 64) {
        char* zr = psm + PM_ZA + t * 64;
        uint32_t sw = (((uint32_t)t >> 1) & 3u) << 4;
        int gi = giS2[t];
        if (gi >= 0) {
            const float4* zp = (const float4*)(z + (size_t)gi * Dd);
            #pragma unroll
            for (int c4 = 0; c4 < 8; c4++) {
                float4 v = zp[c4];
                *(__half2*)(zr + (((uint32_t)(c4 * 8))     ^ sw)) = __floats2half2_rn(v.x, v.y);
                *(__half2*)(zr + (((uint32_t)(c4 * 8 + 4)) ^ sw)) = __floats2half2_rn(v.z, v.w);
            }
        } else {
            #pragma unroll
            for (int c4 = 0; c4 < 8; c4++) {
                *(__half2*)(zr + (((uint32_t)(c4 * 8))     ^ sw)) = __floats2half2_rn(0.f, 0.f);
                *(__half2*)(zr + (((uint32_t)(c4 * 8 + 4)) ^ sw)) = __floats2half2_rn(0.f, 0.f);
            }
        }
    }
    if (t == 0) {
        mbar_expect(mb, 4096);
        bulk_g2s(smb + PM_B,        (const char*)g_w1h + (size_t)(fc * 16 + 0) * 4096, 4096, mb);
        mbar_expect(mb + 8, 4096);
        bulk_g2s(smb + PM_B + 4096, (const char*)g_w1h + (size_t)(fc * 16 + 1) * 4096, 4096, mb + 8);
    }
    __syncthreads();

    int pw[2] = {0, 0};
    for (int q = 0; q < 16; q++) {
        const int buf = q & 1;
        mbar_wait(mb + buf * 8, pw[buf] & 1); pw[buf]++;
        __syncthreads();

        float acc1[2][2][4];
        #pragma unroll
        for (int mt = 0; mt < 2; mt++)
            #pragma unroll
            for (int nt = 0; nt < 2; nt++)
                #pragma unroll
                for (int e = 0; e < 4; e++) acc1[mt][nt][e] = 0.f;

        const uint32_t bbase = smb + PM_B + (uint32_t)buf * 4096u;
        #pragma unroll
        for (int kk = 0; kk < 2; kk++) {
            const uint32_t cb = (uint32_t)((kk * 16 + (mg >> 1) * 8) * 2);
            uint32_t bf[4];
            {
                int nh = wc * 16 + (mg & 1) * 8 + mrow;
                ldsm4(bf, bbase + (uint32_t)nh * 64u + (cb ^ ((((uint32_t)nh >> 1) & 3u) << 4)));
            }
            #pragma unroll
            for (int mt = 0; mt < 2; mt++) {
                uint32_t af[4];
                int jr = wr * 32 + mt * 16 + (mg & 1) * 8 + mrow;
                ldsm4(af, smb + PM_ZA + (uint32_t)jr * 64u + (cb ^ ((((uint32_t)jr >> 1) & 3u) << 4)));
                mma16816(acc1[mt][0], af, bf[0], bf[2]);
                mma16816(acc1[mt][1], af, bf[1], bf[3]);
            }
        }

        #pragma unroll
        for (int mt = 0; mt < 2; mt++)
            #pragma unroll
            for (int nt = 0; nt < 2; nt++) {
                int rl = wr * 32 + mt * 16 + lr;
                int hl = wc * 16 + nt * 8 + lc;
                uint32_t sw = ((uint32_t)rl & 7u) << 4;
                *(__half2*)(psm + PM_STG + rl * 128 + (((uint32_t)(hl * 2)) ^ sw))
                    = __floats2half2_rn(acc1[mt][nt][0], acc1[mt][nt][1]);
                *(__half2*)(psm + PM_STG + (rl + 8) * 128 + (((uint32_t)(hl * 2)) ^ sw))
                    = __floats2half2_rn(acc1[mt][nt][2], acc1[mt][nt][3]);
            }
        __syncthreads();

        if (t == 0 && q + 2 < 16) {
            mbar_expect(mb + buf * 8, 4096);
            bulk_g2s(smb + PM_B + (uint32_t)buf * 4096u,
                     (const char*)g_w1h + (size_t)(fc * 16 + q + 2) * 4096, 4096, mb + buf * 8);
        }

        const int qg = fc * 16 + q;
        #pragma unroll
        for (int l = 0; l < 2; l++) {
            int idx = t + 256 * l;
            int sl = idx >> 3, qt = idx & 7;
            int s = it * 64 + sl;
            if (s < total) {
                uint4 v = *(const uint4*)(psm + PM_STG + sl * 128 + ((qt * 16) ^ ((sl & 7) << 4)));
                *(uint4*)((char*)g_tmph + (size_t)s * 32768 + qg * 128 + qt * 16) = v;
            }
        }
    }
}

// ---------------- main kernel (persistent) ----------------
// dyn smem: zjS 4K @0 | tmpS 32K @4096 | W2 2x16K @36864 | h1 2x8K @69632 = 86016
#define ZJ_OFF  0
#define TMP_OFF 4096
#define W2_OFF  36864
#define H1_OFF  69632
#define MAIN_SMEM 86016

__global__ void __launch_bounds__(256, 2)
decoder_hmma_kernel(const float* __restrict__ z, const float* __restrict__ b1,
                    const float* __restrict__ b2, const float* __restrict__ W3,
                    const float* __restrict__ b3, float* __restrict__ out)
{
    extern __shared__ char dsm[];
    __shared__ float b1s[512], b2s[256], w3s[256], part[64];
    __shared__ int jlS[256];
    __shared__ __align__(8) uint64_t mbars[2];

    const int t    = threadIdx.x;
    const int w    = t >> 5;
    const int lane = t & 31;
    const int wr   = w >> 2;
    const int wc   = w & 3;
    const int lr   = lane >> 2;
    const int lc   = (lane & 3) * 2;
    const int mrow = lane & 7;
    const int mg   = lane >> 3;

    const int U  = g_U;
    const int u0 = (int)(((long long)blockIdx.x * U) / GRID_MAIN);
    const int u1 = (int)(((long long)(blockIdx.x + 1) * U) / GRID_MAIN);
    if (u0 >= u1) return;

    const uint32_t smb = s2u(dsm);
    const uint32_t mb0 = s2u(mbars);

    for (int k = t; k < 512; k += 256) b1s[k] = b1[k];
    b2s[t] = b2[t];
    w3s[t] = W3[t];
    if (t == 0) { mbar_init(mb0, 1); mbar_init(mb0 + 8, 1); }
    __syncthreads();
    if (t == 0) {
        mbar_expect(mb0, 16384);
        bulk_g2s(smb + W2_OFF, (const char*)g_w2t, 16384, mb0);
    }

    const float b3v = b3[0];
    const int totalC = (u1 - u0) * 8;
    int C = 0, pw0 = 0, pw1 = 0;
    int bprev = -1, sprev = -1;

    for (int u = u0; u < u1; u++) {
        const int enc = g_unit[u];
        const int s   = enc >> 4;
        const int jt  = enc & 15;
        const int gi  = g_gilist[s];
        const int b   = gi >> 8;

        if (b != bprev) {
            jlS[t] = g_jlist[b * Nn + t];
            bprev = b;
            __syncthreads();
        }
        const int Kact = g_jcnt[b];

        if (s != sprev) {
            const char* gsrc = (const char*)g_tmph + (size_t)s * 32768;
            #pragma unroll
            for (int r8 = 0; r8 < 8; r8++) {
                int idx = t + 256 * r8;
                int row = idx >> 2, q = idx & 3;
                uint4 v = *(const uint4*)(gsrc + row * 64 + q * 16);
                *(uint4*)(dsm + TMP_OFF + row * 64 + ((q * 16) ^ (((row >> 1) & 3) << 4))) = v;
            }
            sprev = s;
        }

        if (t < 64) {
            part[t] = 0.f;
            int idx = jt * 64 + t;
            char* zr = dsm + ZJ_OFF + t * 64;
            uint32_t sw = (((uint32_t)t >> 1) & 3u) << 4;
            if (idx < Kact) {
                const float4* zp = (const float4*)(z + ((size_t)b * Nn + jlS[idx]) * Dd);
                #pragma unroll
                for (int c4 = 0; c4 < 8; c4++) {
                    float4 v = zp[c4];
                    *(__half2*)(zr + (((uint32_t)(c4 * 8))     ^ sw)) = __floats2half2_rn(v.x, v.y);
                    *(__half2*)(zr + (((uint32_t)(c4 * 8 + 4)) ^ sw)) = __floats2half2_rn(v.z, v.w);
                }
            } else {
                #pragma unroll
                for (int c4 = 0; c4 < 8; c4++) {
                    *(__half2*)(zr + (((uint32_t)(c4 * 8))     ^ sw)) = __floats2half2_rn(0.f, 0.f);
                    *(__half2*)(zr + (((uint32_t)(c4 * 8 + 4)) ^ sw)) = __floats2half2_rn(0.f, 0.f);
                }
            }
        }
        __syncthreads();

        float acc2[2][8][4];
        #pragma unroll
        for (int mt = 0; mt < 2; mt++)
            #pragma unroll
            for (int nt = 0; nt < 8; nt++)
                #pragma unroll
                for (int e = 0; e < 4; e++) acc2[mt][nt][e] = 0.f;

        for (int hc = 0; hc < 8; hc++) {
            float acc1[2][2][4];
            #pragma unroll
            for (int mt = 0; mt < 2; mt++)
                #pragma unroll
                for (int nt = 0; nt < 2; nt++)
                    #pragma unroll
                    for (int e = 0; e < 4; e++) acc1[mt][nt][e] = 0.f;

            #pragma unroll
            for (int kk = 0; kk < 2; kk++) {
                const uint32_t cb = (uint32_t)((kk * 16 + (mg >> 1) * 8) * 2);
                uint32_t bf[4];
                {
                    int nh = hc * 64 + wc * 16 + (mg & 1) * 8 + mrow;
                    ldsm4(bf, smb + TMP_OFF + (uint32_t)nh * 64u + (cb ^ ((((uint32_t)nh >> 1) & 3u) << 4)));
                }
                #pragma unroll
                for (int mt = 0; mt < 2; mt++) {
                    uint32_t af[4];
                    int jr = wr * 32 + mt * 16 + (mg & 1) * 8 + mrow;
                    ldsm4(af, smb + ZJ_OFF + (uint32_t)jr * 64u + (cb ^ ((((uint32_t)jr >> 1) & 3u) << 4)));
                    mma16816(acc1[mt][0], af, bf[0], bf[2]);
                    mma16816(acc1[mt][1], af, bf[1], bf[3]);
                }
            }

            char* h1p = dsm + H1_OFF + (C & 1) * 8192;
            const uint32_t h1b = smb + H1_OFF + (uint32_t)(C & 1) * 8192u;
            #pragma unroll
            for (int mt = 0; mt < 2; mt++)
                #pragma unroll
                for (int nt = 0; nt < 2; nt++) {
                    int rl = wr * 32 + mt * 16 + lr;
                    int hl = wc * 16 + nt * 8 + lc;
                    int hg = hc * 64 + hl;
                    uint32_t sw = ((uint32_t)rl & 7u) << 4;
                    float v0 = fmaxf(acc1[mt][nt][0] + b1s[hg],     0.f);
                    float v1 = fmaxf(acc1[mt][nt][1] + b1s[hg + 1], 0.f);
                    float v2 = fmaxf(acc1[mt][nt][2] + b1s[hg],     0.f);
                    float v3 = fmaxf(acc1[mt][nt][3] + b1s[hg + 1], 0.f);
                    *(__half2*)(h1p + rl * 128 + (((uint32_t)(hl * 2)) ^ sw))       = __floats2half2_rn(v0, v1);
                    *(__half2*)(h1p + (rl + 8) * 128 + (((uint32_t)(hl * 2)) ^ sw)) = __floats2half2_rn(v2, v3);
                }

            mbar_wait(mb0, pw0 & 1); pw0++;
            __syncthreads();

            if (t == 0) {
                mbar_expect(mb0 + 8, 16384);
                bulk_g2s(smb + W2_OFF + 16384,
                         (const char*)g_w2t + ((2 * C + 1) & 15) * 16384, 16384, mb0 + 8);
            }

            #pragma unroll
            for (int kk = 0; kk < 2; kk++) {
                const uint32_t kb = (uint32_t)((kk * 16 + (mg >> 1) * 8) * 2);
                uint32_t bfs[4][4];
                #pragma unroll
                for (int p = 0; p < 4; p++) {
                    int n = wc * 64 + p * 16 + (mg & 1) * 8 + mrow;
                    ldsm4(bfs[p], smb + W2_OFF + (uint32_t)n * 64u + (kb ^ ((((uint32_t)n >> 1) & 3u) << 4)));
                }
                #pragma unroll
                for (int mt = 0; mt < 2; mt++) {
                    uint32_t af[4];
                    int rl = wr * 32 + mt * 16 + (mg & 1) * 8 + mrow;
                    ldsm4(af, h1b + (uint32_t)rl * 128u + (kb ^ (((uint32_t)rl & 7u) << 4)));
                    #pragma unroll
                    for (int p = 0; p < 4; p++) {
                        mma16816(acc2[mt][2 * p],     af, bfs[p][0], bfs[p][2]);
                        mma16816(acc2[mt][2 * p + 1], af, bfs[p][1], bfs[p][3]);
                    }
                }
            }

            __syncthreads();
            if (t == 0 && C + 1 < totalC) {
                mbar_expect(mb0, 16384);
                bulk_g2s(smb + W2_OFF,
                         (const char*)g_w2t + ((2 * C + 2) & 15) * 16384, 16384, mb0);
            }
            mbar_wait(mb0 + 8, pw1 & 1); pw1++;

            #pragma unroll
            for (int kk = 0; kk < 2; kk++) {
                const uint32_t kb  = (uint32_t)((kk * 16 + (mg >> 1) * 8) * 2);
                const uint32_t ccb = kb + 64u;
                uint32_t bfs[4][4];
                #pragma unroll
                for (int p = 0; p < 4; p++) {
                    int n = wc * 64 + p * 16 + (mg & 1) * 8 + mrow;
                    ldsm4(bfs[p], smb + W2_OFF + 16384u + (uint32_t)n * 64u + (kb ^ ((((uint32_t)n >> 1) & 3u) << 4)));
                }
                #pragma unroll
                for (int mt = 0; mt < 2; mt++) {
                    uint32_t af[4];
                    int rl = wr * 32 + mt * 16 + (mg & 1) * 8 + mrow;
                    ldsm4(af, h1b + (uint32_t)rl * 128u + (ccb ^ (((uint32_t)rl & 7u) << 4)));
                    #pragma unroll
                    for (int p = 0; p < 4; p++) {
                        mma16816(acc2[mt][2 * p],     af, bfs[p][0], bfs[p][2]);
                        mma16816(acc2[mt][2 * p + 1], af, bfs[p][1], bfs[p][3]);
                    }
                }
            }
            C++;
        }

        float sacc[2][2] = {{0.f, 0.f}, {0.f, 0.f}};
        #pragma unroll
        for (int mt = 0; mt < 2; mt++)
            #pragma unroll
            for (int nt = 0; nt < 8; nt++) {
                int k = wc * 64 + nt * 8 + lc;
                sacc[mt][0] += fmaxf(acc2[mt][nt][0] + b2s[k],     0.f) * w3s[k]
                             + fmaxf(acc2[mt][nt][1] + b2s[k + 1], 0.f) * w3s[k + 1];
                sacc[mt][1] += fmaxf(acc2[mt][nt][2] + b2s[k],     0.f) * w3s[k]
                             + fmaxf(acc2[mt][nt][3] + b2s[k + 1], 0.f) * w3s[k + 1];
            }
        #pragma unroll
        for (int off = 1; off <= 2; off <<= 1) {
            #pragma unroll
            for (int mt = 0; mt < 2; mt++) {
                sacc[mt][0] += __shfl_xor_sync(0xffffffffu, sacc[mt][0], off);
                sacc[mt][1] += __shfl_xor_sync(0xffffffffu, sacc[mt][1], off);
            }
        }
        if ((lane & 3) == 0) {
            #pragma unroll
            for (int mt = 0; mt < 2; mt++) {
                int r0 = wr * 32 + mt * 16 + lr;
                atomicAdd(&part[r0],     sacc[mt][0]);
                atomicAdd(&part[r0 + 8], sacc[mt][1]);
            }
        }
        __syncthreads();
        if (t < 64) {
            int idx = jt * 64 + t;
            if (idx < Kact) {
                int j = jlS[idx];
                float lg = part[t] + b3v;
                size_t o = (size_t)gi * Nn + j;
                out[o] = 1.f / (1.f + __expf(-lg));
                out[(size_t)Bb * Nn * Nn + o] = lg;
            }
        }
        __syncthreads();
    }
}

extern "C" void kernel_launch(void* const* d_in, const int* in_sizes, int n_in,
                              void* d_out, int out_size)
{
    const float* z   = (const float*)d_in[0];
    const float* mmk = (const float*)d_in[1];
    const float* W1  = (const float*)d_in[3];
    const float* b1  = (const float*)d_in[4];
    const float* W2  = (const float*)d_in[5];
    const float* b2  = (const float*)d_in[6];
    const float* W3  = (const float*)d_in[7];
    const float* b3  = (const float*)d_in[8];
    float* out = (float*)d_out;

    cudaFuncSetAttribute(decoder_hmma_kernel,
                         cudaFuncAttributeMaxDynamicSharedMemorySize, MAIN_SMEM);

    prep_all_kernel<<<896, 256>>>(out, W2, W1);
    prep_mask_kernel<<<1, 1024>>>(mmk);
    prep_tmpmma_kernel<<<dim3(8, 16), 256, PM_SMEM>>>(z);
    decoder_hmma_kernel<<<GRID_MAIN, 256, MAIN_SMEM>>>(z, b1, b2, W3, b3, out);
}